// round 1
// baseline (speedup 1.0000x reference)
#include <cuda_runtime.h>
#include <math.h>

#define BATCH 8
#define CH    128
#define NT    4096
#define NF    2049
#define FPAD  2064
#define SQRTN 64.0f
#define ATT_SCALE 0.08838834764831845f  /* 1/sqrt(128) */

// ---------------- scratch (device globals; no allocation in kernel_launch) ----
__device__ float g_Xr[BATCH*CH*FPAD];
__device__ float g_Xi[BATCH*CH*FPAD];
__device__ float g_Kr[BATCH*CH*FPAD];
__device__ float g_Ki[BATCH*CH*FPAD];
__device__ float g_Vr[BATCH*CH*FPAD];
__device__ float g_Vi[BATCH*CH*FPAD];
__device__ float g_Or[BATCH*CH*FPAD];
__device__ float g_Oi[BATCH*CH*FPAD];
__device__ float g_energy[BATCH*NF];
__device__ float g_normv[BATCH*NF];
__device__ float g_med[BATCH];
__device__ float g_thr[1];

// packed f32x2 FMA (FFMA2) — only reachable via PTX fma.rn.f32x2
__device__ __forceinline__ float2 fma2(float2 a, float2 b, float2 c) {
    float2 d;
    asm("{\n\t"
        ".reg .b64 ra, rb, rc, rd;\n\t"
        "mov.b64 ra, {%2,%3};\n\t"
        "mov.b64 rb, {%4,%5};\n\t"
        "mov.b64 rc, {%6,%7};\n\t"
        "fma.rn.f32x2 rd, ra, rb, rc;\n\t"
        "mov.b64 {%0,%1}, rd;\n\t"
        "}"
        : "=f"(d.x), "=f"(d.y)
        : "f"(a.x), "f"(a.y), "f"(b.x), "f"(b.y), "f"(c.x), "f"(c.y));
    return d;
}

// ---------------- Stockham radix-2 FFT of 4096 in shared memory ---------------
// SIGN = -1 forward, +1 inverse (unnormalized). 512 threads. Result ends in bufA.
template <int SIGN>
__device__ __forceinline__ void fft4096(float2* bufA, float2* bufB) {
    float2* src = bufA;
    float2* dst = bufB;
#pragma unroll 1
    for (int s = 0; s < 12; s++) {
        int L = 1 << s;
        __syncthreads();
        for (int i = threadIdx.x; i < 2048; i += 512) {
            int k = i & (L - 1);
            int j = i >> s;
            float2 u = src[i];
            float2 v = src[i + 2048];
            float ang = (float)SIGN * 3.14159265358979323846f * (float)k / (float)L;
            float sw, cw;
            __sincosf(ang, &sw, &cw);
            float2 wv = make_float2(cw * v.x - sw * v.y, cw * v.y + sw * v.x);
            int o = (j << (s + 1)) + k;
            dst[o]     = make_float2(u.x + wv.x, u.y + wv.y);
            dst[o + L] = make_float2(u.x - wv.x, u.y - wv.y);
        }
        float2* t = src; src = dst; dst = t;
    }
    __syncthreads();
    // 12 swaps (even) -> result in bufA
}

// ---------------- forward rfft: x_in[b][c][:] -> Xr/Xi planes [b][c][f] -------
__global__ __launch_bounds__(512) void k_fft_fwd(const float* __restrict__ x_in) {
    extern __shared__ float2 sm2[];
    float2* A = sm2;
    float2* Bb = sm2 + 4096;
    int bc = blockIdx.x;
    const float* xrow = x_in + (size_t)bc * NT;
    for (int k = threadIdx.x; k < 4096; k += 512) A[k] = make_float2(xrow[k], 0.f);
    fft4096<-1>(A, Bb);
    const float s = 1.0f / SQRTN;
    size_t base = (size_t)bc * FPAD;
    for (int f = threadIdx.x; f < NF; f += 512) {
        g_Xr[base + f] = A[f].x * s;
        g_Xi[base + f] = A[f].y * s;
    }
}

// ---------------- K/V GEMM in frequency domain --------------------------------
// out[m][f] = sum_c W[m][c] * X[c][f];  m in [0,256): 0..127 K (W_K), 128..255 V (W_V)
// bin f==0 of real plane gets + SQRTN*bias.
__global__ __launch_bounds__(256) void k_gemm_kv(const float* __restrict__ WK,
                                                 const float* __restrict__ WV,
                                                 const float* __restrict__ bK,
                                                 const float* __restrict__ bV) {
    __shared__ float As[16][68];
    __shared__ float Bs[16][68];
    int ft = blockIdx.x;            // 0..32
    int mt = blockIdx.y;            // 0..3
    int bz = blockIdx.z;            // b*2+plane
    int b = bz >> 1, plane = bz & 1;
    const float* X = (plane ? g_Xi : g_Xr) + (size_t)b * CH * FPAD;
    int tid = threadIdx.x;
    int ty = tid >> 4, tx = tid & 15;
    int f0 = ft * 64, m0 = mt * 64;
    float acc[4][4] = {};
    for (int k0 = 0; k0 < 128; k0 += 16) {
        for (int l = tid; l < 1024; l += 256) {
            int m = l >> 4, k = l & 15;
            int gm = m0 + m;
            const float* W = (gm < 128) ? WK : WV;
            As[k][m] = W[(gm & 127) * 128 + k0 + k];
        }
        for (int l = tid; l < 1024; l += 256) {
            int k = l >> 6, f = l & 63;
            int gf = f0 + f;
            Bs[k][f] = (gf < NF) ? X[(size_t)(k0 + k) * FPAD + gf] : 0.f;
        }
        __syncthreads();
#pragma unroll
        for (int kk = 0; kk < 16; kk++) {
            float a[4], bb[4];
#pragma unroll
            for (int i = 0; i < 4; i++) a[i] = As[kk][ty + 16 * i];
#pragma unroll
            for (int j = 0; j < 4; j++) bb[j] = Bs[kk][tx + 16 * j];
#pragma unroll
            for (int i = 0; i < 4; i++)
#pragma unroll
                for (int j = 0; j < 4; j++) acc[i][j] += a[i] * bb[j];
        }
        __syncthreads();
    }
#pragma unroll
    for (int i = 0; i < 4; i++) {
        int gm = m0 + ty + 16 * i;
        float* outp;
        if (gm < 128) outp = plane ? g_Ki : g_Kr;
        else          outp = plane ? g_Vi : g_Vr;
        float bias = (gm < 128) ? bK[gm] : bV[gm - 128];
        size_t rb = (size_t)b * CH * FPAD + (size_t)(gm & 127) * FPAD;
#pragma unroll
        for (int j = 0; j < 4; j++) {
            int gf = f0 + tx + 16 * j;
            if (gf < NF) {
                float v = acc[i][j];
                if (plane == 0 && gf == 0) v += SQRTN * bias;
                outp[rb + gf] = v;
            }
        }
    }
}

// ---------------- flash attention over frequency bins --------------------------
// S[f,g] = sum_c Q[f,c]*K[g,c] (complex, no conj); softmax(|S|*scale) over g;
// O[f,c] = sum_g P[f,g]*V[g,c] / l[f].
#define AT_QR 0
#define AT_QI 8192
#define AT_KVR 16384
#define AT_KVI (16384 + 8576)
#define AT_P   (16384 + 2*8576)
#define AT_FLOATS (16384 + 2*8576 + 4096)

__global__ __launch_bounds__(256, 1) void k_attn() {
    extern __shared__ float sm[];
    float* Qr = sm + AT_QR;
    float* Qi = sm + AT_QI;
    float* KVr = sm + AT_KVR;
    float* KVi = sm + AT_KVI;
    float* P  = sm + AT_P;
    int b = blockIdx.y;
    int f0 = blockIdx.x * 64;
    const size_t base = (size_t)b * CH * FPAD;
    int tid = threadIdx.x;
    int ty = tid >> 4, tx = tid & 15;
    int fidx[4] = {2 * ty, 2 * ty + 1, 2 * ty + 32, 2 * ty + 33};

    // load Q tile [c][f]
    for (int l = tid; l < 8192; l += 256) {
        int c = l >> 6, f = l & 63;
        int gf = f0 + f;
        float vr = 0.f, vi = 0.f;
        if (gf < NF) { vr = g_Xr[base + (size_t)c * FPAD + gf]; vi = g_Xi[base + (size_t)c * FPAD + gf]; }
        Qr[l] = vr; Qi[l] = vi;
    }

    float2 or2[4][4], oi2[4][4];
#pragma unroll
    for (int i = 0; i < 4; i++)
#pragma unroll
        for (int q = 0; q < 4; q++) { or2[i][q] = make_float2(0.f, 0.f); oi2[i][q] = make_float2(0.f, 0.f); }
    float mrow[4] = {-1e30f, -1e30f, -1e30f, -1e30f};
    float lrow[4] = {0.f, 0.f, 0.f, 0.f};

    for (int g0 = 0; g0 < NF; g0 += 64) {
        // load K tile [c][g]
        for (int l = tid; l < 8192; l += 256) {
            int c = l >> 6, g = l & 63;
            int gg = g0 + g;
            float vr = 0.f, vi = 0.f;
            if (gg < NF) { vr = g_Kr[base + (size_t)c * FPAD + gg]; vi = g_Ki[base + (size_t)c * FPAD + gg]; }
            KVr[l] = vr; KVi[l] = vi;
        }
        __syncthreads();

        float2 sr[4][2], si[4][2];
#pragma unroll
        for (int i = 0; i < 4; i++)
#pragma unroll
            for (int j = 0; j < 2; j++) { sr[i][j] = make_float2(0.f, 0.f); si[i][j] = make_float2(0.f, 0.f); }

#pragma unroll 4
        for (int c = 0; c < 128; c++) {
            const float2* qr = (const float2*)(Qr + c * 64);
            const float2* qi = (const float2*)(Qi + c * 64);
            const float2* kr = (const float2*)(KVr + c * 64);
            const float2* ki = (const float2*)(KVi + c * 64);
            float2 q01r = qr[ty], q23r = qr[ty + 16];
            float2 q01i = qi[ty], q23i = qi[ty + 16];
            float2 k0r = kr[tx], k1r = kr[tx + 16];
            float2 k0i = ki[tx], k1i = ki[tx + 16];
            float qrv[4] = {q01r.x, q01r.y, q23r.x, q23r.y};
            float qiv[4] = {q01i.x, q01i.y, q23i.x, q23i.y};
#pragma unroll
            for (int i = 0; i < 4; i++) {
                float2 a  = make_float2(qrv[i], qrv[i]);
                float2 bn = make_float2(-qiv[i], -qiv[i]);
                float2 bp = make_float2(qiv[i], qiv[i]);
                sr[i][0] = fma2(a, k0r, sr[i][0]);  sr[i][0] = fma2(bn, k0i, sr[i][0]);
                sr[i][1] = fma2(a, k1r, sr[i][1]);  sr[i][1] = fma2(bn, k1i, sr[i][1]);
                si[i][0] = fma2(a, k0i, si[i][0]);  si[i][0] = fma2(bp, k0r, si[i][0]);
                si[i][1] = fma2(a, k1i, si[i][1]);  si[i][1] = fma2(bp, k1r, si[i][1]);
            }
        }

        // magnitudes, column validity
        int gcol[4] = {g0 + 2 * tx, g0 + 2 * tx + 1, g0 + 2 * tx + 32, g0 + 2 * tx + 33};
        float mag[4][4];
#pragma unroll
        for (int i = 0; i < 4; i++) {
            mag[i][0] = sqrtf(sr[i][0].x * sr[i][0].x + si[i][0].x * si[i][0].x) * ATT_SCALE;
            mag[i][1] = sqrtf(sr[i][0].y * sr[i][0].y + si[i][0].y * si[i][0].y) * ATT_SCALE;
            mag[i][2] = sqrtf(sr[i][1].x * sr[i][1].x + si[i][1].x * si[i][1].x) * ATT_SCALE;
            mag[i][3] = sqrtf(sr[i][1].y * sr[i][1].y + si[i][1].y * si[i][1].y) * ATT_SCALE;
#pragma unroll
            for (int j = 0; j < 4; j++) if (gcol[j] >= NF) mag[i][j] = -1e30f;
        }

        // online softmax update
        float p[4][4];
#pragma unroll
        for (int i = 0; i < 4; i++) {
            float t = fmaxf(fmaxf(mag[i][0], mag[i][1]), fmaxf(mag[i][2], mag[i][3]));
#pragma unroll
            for (int m = 8; m >= 1; m >>= 1) t = fmaxf(t, __shfl_xor_sync(0xffffffffu, t, m));
            float mnew = fmaxf(mrow[i], t);
            float corr = __expf(mrow[i] - mnew);
            mrow[i] = mnew;
            float ps = 0.f;
#pragma unroll
            for (int j = 0; j < 4; j++) { p[i][j] = __expf(mag[i][j] - mnew); ps += p[i][j]; }
#pragma unroll
            for (int m = 8; m >= 1; m >>= 1) ps += __shfl_xor_sync(0xffffffffu, ps, m);
            lrow[i] = lrow[i] * corr + ps;
#pragma unroll
            for (int q = 0; q < 4; q++) {
                or2[i][q].x *= corr; or2[i][q].y *= corr;
                oi2[i][q].x *= corr; oi2[i][q].y *= corr;
            }
            // stage P
            ((float2*)(P + fidx[i] * 64))[tx]      = make_float2(p[i][0], p[i][1]);
            ((float2*)(P + fidx[i] * 64))[tx + 16] = make_float2(p[i][2], p[i][3]);
        }
        __syncthreads();   // S consumed everywhere; safe to overwrite K with V; P visible after next sync

        // load V tile transposed: KV[g*134 + c]
        for (int l = tid; l < 8192; l += 256) {
            int c = l >> 6, g = l & 63;
            int gg = g0 + g;
            float vr = 0.f, vi = 0.f;
            if (gg < NF) { vr = g_Vr[base + (size_t)c * FPAD + gg]; vi = g_Vi[base + (size_t)c * FPAD + gg]; }
            KVr[g * 134 + c] = vr; KVi[g * 134 + c] = vi;
        }
        __syncthreads();

        // O += P * V
#pragma unroll 2
        for (int g = 0; g < 64; g++) {
            float pv[4];
#pragma unroll
            for (int i = 0; i < 4; i++) pv[i] = P[fidx[i] * 64 + g];
            const float2* vr = (const float2*)(KVr + g * 134);
            const float2* vi = (const float2*)(KVi + g * 134);
            float2 vr2[4], vi2[4];
#pragma unroll
            for (int q = 0; q < 4; q++) { vr2[q] = vr[tx + 16 * q]; vi2[q] = vi[tx + 16 * q]; }
#pragma unroll
            for (int i = 0; i < 4; i++) {
                float2 pp = make_float2(pv[i], pv[i]);
#pragma unroll
                for (int q = 0; q < 4; q++) {
                    or2[i][q] = fma2(pp, vr2[q], or2[i][q]);
                    oi2[i][q] = fma2(pp, vi2[q], oi2[i][q]);
                }
            }
        }
        __syncthreads();   // V/P consumed; next iteration reloads K
    }

    float invl[4];
#pragma unroll
    for (int i = 0; i < 4; i++) invl[i] = 1.0f / lrow[i];

    // stage O[f][c] (pad 130) into Q smem (free now), write coalesced rows [c][f]
    float* Os = Qr;  // spans Qr+Qi = 16384 floats; need 64*130 = 8320
    int wid = tid >> 5, lane = tid & 31;
    for (int plane = 0; plane < 2; plane++) {
#pragma unroll
        for (int i = 0; i < 4; i++)
#pragma unroll
            for (int q = 0; q < 4; q++) {
                float2 v = plane ? oi2[i][q] : or2[i][q];
                v.x *= invl[i]; v.y *= invl[i];
                ((float2*)(Os + fidx[i] * 130))[tx + 16 * q] = v;
            }
        __syncthreads();
        float* outp = plane ? g_Oi : g_Or;
        for (int c = wid; c < 128; c += 8) {
#pragma unroll
            for (int h = 0; h < 2; h++) {
                int f = lane + 32 * h;
                int gf = f0 + f;
                if (gf < NF) outp[base + (size_t)c * FPAD + gf] = Os[f * 130 + c];
            }
        }
        __syncthreads();
    }
}

// ---------------- energy / median / normalize / quantile / mask ----------------
__global__ __launch_bounds__(128) void k_energy() {
    int b = blockIdx.y;
    int f = blockIdx.x * 128 + threadIdx.x;
    if (f >= NF) return;
    size_t base = (size_t)b * CH * FPAD + f;
    float e = 0.f;
#pragma unroll 4
    for (int c = 0; c < 128; c++) {
        float r = g_Xr[base + (size_t)c * FPAD];
        float im = g_Xi[base + (size_t)c * FPAD];
        e += r * r + im * im;
    }
    g_energy[b * NF + f] = e;
}

__global__ __launch_bounds__(1024) void k_median() {
    __shared__ float s[4096];
    int b = blockIdx.x;
    for (int i = threadIdx.x; i < 4096; i += 1024) s[i] = (i < NF) ? g_energy[b * NF + i] : 1e30f;
    __syncthreads();
    for (int k = 2; k <= 4096; k <<= 1) {
        for (int j = k >> 1; j > 0; j >>= 1) {
            for (int i = threadIdx.x; i < 4096; i += 1024) {
                int ixj = i ^ j;
                if (ixj > i) {
                    bool up = ((i & k) == 0);
                    float a = s[i], bv = s[ixj];
                    if (up ? (a > bv) : (a < bv)) { s[i] = bv; s[ixj] = a; }
                }
            }
            __syncthreads();
        }
    }
    if (threadIdx.x == 0) g_med[b] = s[1024];
}

__global__ __launch_bounds__(256) void k_normalize() {
    int idx = blockIdx.x * 256 + threadIdx.x;
    if (idx >= BATCH * NF) return;
    int b = idx / NF;
    g_normv[idx] = g_energy[idx] / (g_med[b] + 1e-6f);
}

__global__ __launch_bounds__(1024) void k_quantile(const float* __restrict__ qparam) {
    extern __shared__ float s[];
    const int n = BATCH * NF;       // 16392
    const int NP = 32768;
    for (int i = threadIdx.x; i < NP; i += 1024) s[i] = (i < n) ? g_normv[i] : 1e30f;
    __syncthreads();
    for (int k = 2; k <= NP; k <<= 1) {
        for (int j = k >> 1; j > 0; j >>= 1) {
            for (int i = threadIdx.x; i < NP; i += 1024) {
                int ixj = i ^ j;
                if (ixj > i) {
                    bool up = ((i & k) == 0);
                    float a = s[i], bv = s[ixj];
                    if (up ? (a > bv) : (a < bv)) { s[i] = bv; s[ixj] = a; }
                }
            }
            __syncthreads();
        }
    }
    if (threadIdx.x == 0) {
        float q = qparam[0];
        float pos = q * (float)(n - 1);
        int lo = (int)floorf(pos);
        if (lo < 0) lo = 0;
        if (lo > n - 2) lo = n - 2;
        float frac = pos - (float)lo;
        g_thr[0] = s[lo] + (s[lo + 1] - s[lo]) * frac;
    }
}

__global__ __launch_bounds__(256) void k_hifreq(const float* __restrict__ w_high) {
    int bc = blockIdx.x;
    int b = bc >> 7, c = bc & 127;
    float whr = w_high[c * 2], whi = w_high[c * 2 + 1];
    float t = g_thr[0];
    size_t base = (size_t)bc * FPAD;
    for (int f = threadIdx.x; f < NF; f += 256) {
        if (g_normv[b * NF + f] > t) {
            float xr = g_Xr[base + f], xi = g_Xi[base + f];
            g_Or[base + f] += xr * whr - xi * whi;
            g_Oi[base + f] += xr * whi + xi * whr;
        }
    }
}

// ---------------- inverse rfft -> output (B,C,N) ------------------------------
__global__ __launch_bounds__(512) void k_ifft(float* __restrict__ out) {
    extern __shared__ float2 sm2[];
    float2* A = sm2;
    float2* Bb = sm2 + 4096;
    int bc = blockIdx.x;
    size_t base = (size_t)bc * FPAD;
    for (int k = threadIdx.x; k < 4096; k += 512) {
        int kk = (k <= 2048) ? k : (4096 - k);
        float sgn = (k <= 2048) ? 1.f : -1.f;
        A[k] = make_float2(g_Or[base + kk], sgn * g_Oi[base + kk]);
    }
    fft4096<1>(A, Bb);
    const float s = 1.0f / SQRTN;
    float* orow = out + (size_t)bc * NT;
    for (int n = threadIdx.x; n < 4096; n += 512) orow[n] = A[n].x * s;
}

// ---------------- launch -------------------------------------------------------
extern "C" void kernel_launch(void* const* d_in, const int* in_sizes, int n_in,
                              void* d_out, int out_size) {
    const float* x_in   = (const float*)d_in[0];
    const float* W_K    = (const float*)d_in[1];
    const float* b_K    = (const float*)d_in[2];
    const float* W_V    = (const float*)d_in[3];
    const float* b_V    = (const float*)d_in[4];
    const float* w_high = (const float*)d_in[5];
    const float* qparam = (const float*)d_in[6];
    float* out = (float*)d_out;

    const int fft_smem = 2 * 4096 * sizeof(float2);        // 65536
    const int att_smem = AT_FLOATS * sizeof(float);        // ~150 KB
    const int qnt_smem = 32768 * sizeof(float);            // 131072
    cudaFuncSetAttribute(k_fft_fwd,  cudaFuncAttributeMaxDynamicSharedMemorySize, fft_smem);
    cudaFuncSetAttribute(k_ifft,     cudaFuncAttributeMaxDynamicSharedMemorySize, fft_smem);
    cudaFuncSetAttribute(k_attn,     cudaFuncAttributeMaxDynamicSharedMemorySize, att_smem);
    cudaFuncSetAttribute(k_quantile, cudaFuncAttributeMaxDynamicSharedMemorySize, qnt_smem);

    k_fft_fwd<<<BATCH * CH, 512, fft_smem>>>(x_in);
    k_gemm_kv<<<dim3(33, 4, 16), 256>>>(W_K, W_V, b_K, b_V);
    k_attn<<<dim3(33, BATCH), 256, att_smem>>>();
    k_energy<<<dim3(17, BATCH), 128>>>();
    k_median<<<BATCH, 1024>>>();
    k_normalize<<<(BATCH * NF + 255) / 256, 256>>>();
    k_quantile<<<1, 1024, qnt_smem>>>(qparam);
    k_hifreq<<<BATCH * CH, 256>>>(w_high);
    k_ifft<<<BATCH * CH, 512, fft_smem>>>(out);
}

// round 3
// speedup vs baseline: 1.9606x; 1.9606x over previous
#include <cuda_runtime.h>
#include <cuda_bf16.h>
#include <math.h>
#include <stdint.h>

#define BATCH 8
#define CH    128
#define NT    4096
#define NF    2049
#define FPAD  2064
#define FT    2176          /* padded F for tensor path: 17*128 */
#define SQRTN 64.0f
#define ATT_SCALE 0.08838834764831845f  /* 1/sqrt(128) */

// tcgen05 PTX is only legal in the arch-specific (sm_103a) compile pass.
#if defined(__CUDA_ARCH_FEAT_SM103_ALL) || defined(__CUDA_ARCH_FEAT_SM100_ALL)
#define TC_ENABLED 1
#else
#define TC_ENABLED 0
#endif

// ---------------- scratch (device globals; no allocation in kernel_launch) ----
__device__ float g_Xr[BATCH*CH*FPAD];
__device__ float g_Xi[BATCH*CH*FPAD];
__device__ float g_Kr[BATCH*CH*FPAD];
__device__ float g_Ki[BATCH*CH*FPAD];
__device__ float g_Vr[BATCH*CH*FPAD];
__device__ float g_Vi[BATCH*CH*FPAD];
__device__ float g_Or[BATCH*CH*FPAD];
__device__ float g_Oi[BATCH*CH*FPAD];
__device__ float g_energy[BATCH*NF];
__device__ float g_normv[BATCH*NF];
__device__ float g_med[BATCH];
__device__ float g_thr[1];

// bf16 split planes for tensor cores
#define QKN ((size_t)BATCH*FT*CH)     /* [b][f][c] */
#define VN  ((size_t)BATCH*CH*FT)     /* [b][c][g] */
#define PN  ((size_t)BATCH*FT*FT)     /* [b][f][g] */
__device__ __align__(256) __nv_bfloat16 g_qrh[QKN], g_qrl[QKN];
__device__ __align__(256) __nv_bfloat16 g_qih[QKN], g_qil[QKN];
__device__ __align__(256) __nv_bfloat16 g_qnh[QKN], g_qnl[QKN];   /* -Qi */
__device__ __align__(256) __nv_bfloat16 g_krh[QKN], g_krl[QKN];
__device__ __align__(256) __nv_bfloat16 g_kih[QKN], g_kil[QKN];
__device__ __align__(256) __nv_bfloat16 g_vrh[VN],  g_vrl[VN];
__device__ __align__(256) __nv_bfloat16 g_vih[VN],  g_vil[VN];
__device__ __align__(256) __nv_bfloat16 g_ph[PN],   g_pl[PN];
__device__ __align__(256) float g_S[PN];

// ================= tcgen05 helpers (feature-gated) ============================
__device__ __forceinline__ uint32_t smem_u32(const void* p) {
    uint32_t a;
    asm("{ .reg .u64 t; cvta.to.shared.u64 t, %1; cvt.u32.u64 %0, t; }" : "=r"(a) : "l"(p));
    return a;
}
__device__ __forceinline__ uint32_t elect_one() {
    uint32_t p;
    asm volatile("{ .reg .pred p; elect.sync _|p, 0xFFFFFFFF; selp.b32 %0, 1, 0, p; }" : "=r"(p));
    return p;
}
__device__ __forceinline__ void tc_alloc(uint32_t sa, uint32_t n) {
#if TC_ENABLED
    asm volatile("tcgen05.alloc.cta_group::1.sync.aligned.shared::cta.b32 [%0], %1;" :: "r"(sa), "r"(n) : "memory");
#endif
}
__device__ __forceinline__ void tc_dealloc(uint32_t tm, uint32_t n) {
#if TC_ENABLED
    asm volatile("tcgen05.dealloc.cta_group::1.sync.aligned.b32 %0, %1;" :: "r"(tm), "r"(n));
#endif
}
__device__ __forceinline__ void tc_commit(uint32_t mb) {
#if TC_ENABLED
    asm volatile("tcgen05.commit.cta_group::1.mbarrier::arrive::one.shared::cluster.b64 [%0];" :: "r"(mb) : "memory");
#endif
}
__device__ __forceinline__ void tc_wait_ld() {
#if TC_ENABLED
    asm volatile("tcgen05.wait::ld.sync.aligned;" ::: "memory");
#endif
}
__device__ __forceinline__ void tc_fence_after() {
#if TC_ENABLED
    asm volatile("tcgen05.fence::after_thread_sync;" ::: "memory");
#endif
}
__device__ __forceinline__ void tc_ld_x32(uint32_t* r, uint32_t ta) {
#if TC_ENABLED
    asm volatile("tcgen05.ld.sync.aligned.32x32b.x32.b32 "
        "{%0, %1, %2, %3, %4, %5, %6, %7, %8, %9, %10, %11, %12, %13, %14, %15, "
        " %16, %17, %18, %19, %20, %21, %22, %23, %24, %25, %26, %27, %28, %29, %30, %31}, [%32];"
        : "=r"(r[0]),  "=r"(r[1]),  "=r"(r[2]),  "=r"(r[3]),
          "=r"(r[4]),  "=r"(r[5]),  "=r"(r[6]),  "=r"(r[7]),
          "=r"(r[8]),  "=r"(r[9]),  "=r"(r[10]), "=r"(r[11]),
          "=r"(r[12]), "=r"(r[13]), "=r"(r[14]), "=r"(r[15]),
          "=r"(r[16]), "=r"(r[17]), "=r"(r[18]), "=r"(r[19]),
          "=r"(r[20]), "=r"(r[21]), "=r"(r[22]), "=r"(r[23]),
          "=r"(r[24]), "=r"(r[25]), "=r"(r[26]), "=r"(r[27]),
          "=r"(r[28]), "=r"(r[29]), "=r"(r[30]), "=r"(r[31])
        : "r"(ta));
#else
    for (int i = 0; i < 32; i++) r[i] = 0u;
#endif
}

#define MBAR_INIT(mb, c)  asm volatile("mbarrier.init.shared.b64 [%0], %1;" :: "r"((uint32_t)(mb)), "r"((uint32_t)(c)) : "memory")
#define MBAR_INVAL(mb)    asm volatile("mbarrier.inval.shared.b64 [%0];" :: "r"((uint32_t)(mb)) : "memory")
__device__ __forceinline__ void mbar_wait(uint32_t mb, uint32_t ph) {
#if TC_ENABLED
    asm volatile("{\n\t.reg .pred P1;\n\tWL_%=:\n\t"
        "mbarrier.try_wait.parity.acquire.cta.shared::cta.b64 P1, [%0], %1, 0x989680;\n\t"
        "@P1 bra.uni WD_%=;\n\tbra.uni WL_%=;\n\tWD_%=:\n\t}"
        :: "r"(mb), "r"(ph) : "memory");
#endif
}
#define FENCE_ASYNC()     asm volatile("fence.proxy.async.shared::cta;" ::: "memory")

static constexpr uint64_t DESC_BASE_SW128 =
    (uint64_t(2) << 61) | (uint64_t(1) << 46) | (uint64_t(64) << 32) | (uint64_t(1) << 16);
#define MK_DESC(a) (DESC_BASE_SW128 | ((uint64_t)(((uint32_t)(a)) >> 4) & 0x3FFF))

// idesc kind::f16: F32 acc, BF16 a/b, K-major both, N=128, M=128
#define QK_IDESC ((1u<<4)|(1u<<7)|(1u<<10)|((128u/8u)<<17)|((128u/16u)<<24))

__device__ __forceinline__ void mma_f16_ss(uint32_t d, uint64_t ad, uint64_t bd, uint32_t idesc, int en) {
#if TC_ENABLED
    asm volatile("{\n\t.reg .pred p;\n\tsetp.ne.u32 p, %4, 0;\n\t"
        "tcgen05.mma.cta_group::1.kind::f16 [%0], %1, %2, %3, {%5, %5, %5, %5}, p;\n\t}"
        :: "r"(d), "l"(ad), "l"(bd), "r"(idesc), "r"((uint32_t)en), "r"(0u) : "memory");
#endif
}

// smem layout for both MMA kernels (bytes)
#define R_A    0
#define R_B0   65536
#define R_B1   131072
#define R_CTRL 196608
#define MMA_SMEM_BYTES (196608 + 16)
#define STAGE0 0
#define STAGE1 69632

// load 4 tiles (hi/lo × khalf) of [128 rows][64 bf16] with SW128 swizzle
__device__ __forceinline__ void load_tile_pair(char* sm, int region,
        const __nv_bfloat16* __restrict__ hi, const __nv_bfloat16* __restrict__ lo,
        size_t rbase, int rstride) {
    int t = threadIdx.x;
#pragma unroll
    for (int sp = 0; sp < 2; sp++) {
        const __nv_bfloat16* src = sp ? lo : hi;
#pragma unroll
        for (int kh = 0; kh < 2; kh++) {
#pragma unroll
            for (int i = 0; i < 4; i++) {
                int idx = t + i * 256;
                int row = idx >> 3, ch = idx & 7;
                uint4 v = *(const uint4*)(src + rbase + (size_t)row * rstride + kh * 64 + ch * 8);
                uint32_t off = (uint32_t)(row * 128 + ch * 16);
                off ^= (off >> 3) & 0x70;
                *(uint4*)(sm + region + (sp * 2 + kh) * 16384 + off) = v;
            }
        }
    }
}

// 3-chain split MMA: (hi,hi),(hi,lo),(lo,hi), K=128 = 2 khalves × 4 K16 steps
__device__ __forceinline__ void mma_pair(uint32_t d, uint32_t smb, int aoff, int boff, int first) {
    const int asp[3] = {0, 0, 1};
    const int bsp[3] = {0, 1, 0};
#pragma unroll
    for (int s = 0; s < 3; s++) {
#pragma unroll
        for (int kh = 0; kh < 2; kh++) {
            uint64_t ad = MK_DESC(smb + aoff + (asp[s] * 2 + kh) * 16384);
            uint64_t bd = MK_DESC(smb + boff + (bsp[s] * 2 + kh) * 16384);
#pragma unroll
            for (int ks = 0; ks < 4; ks++) {
                int en = !(first && s == 0 && kh == 0 && ks == 0);
                mma_f16_ss(d, ad + ks * 2, bd + ks * 2, QK_IDESC, en);
            }
        }
    }
}

// ---------------- Stockham radix-2 FFT of 4096 in shared memory ---------------
template <int SIGN>
__device__ __forceinline__ void fft4096(float2* bufA, float2* bufB) {
    float2* src = bufA;
    float2* dst = bufB;
#pragma unroll 1
    for (int s = 0; s < 12; s++) {
        int L = 1 << s;
        __syncthreads();
        for (int i = threadIdx.x; i < 2048; i += 512) {
            int k = i & (L - 1);
            int j = i >> s;
            float2 u = src[i];
            float2 v = src[i + 2048];
            float ang = (float)SIGN * 3.14159265358979323846f * (float)k / (float)L;
            float sw, cw;
            __sincosf(ang, &sw, &cw);
            float2 wv = make_float2(cw * v.x - sw * v.y, cw * v.y + sw * v.x);
            int o = (j << (s + 1)) + k;
            dst[o]     = make_float2(u.x + wv.x, u.y + wv.y);
            dst[o + L] = make_float2(u.x - wv.x, u.y - wv.y);
        }
        float2* t = src; src = dst; dst = t;
    }
    __syncthreads();
}

__global__ __launch_bounds__(512) void k_fft_fwd(const float* __restrict__ x_in) {
    extern __shared__ float2 sm2[];
    float2* A = sm2;
    float2* Bb = sm2 + 4096;
    int bc = blockIdx.x;
    const float* xrow = x_in + (size_t)bc * NT;
    for (int k = threadIdx.x; k < 4096; k += 512) A[k] = make_float2(xrow[k], 0.f);
    fft4096<-1>(A, Bb);
    const float s = 1.0f / SQRTN;
    size_t base = (size_t)bc * FPAD;
    for (int f = threadIdx.x; f < NF; f += 512) {
        g_Xr[base + f] = A[f].x * s;
        g_Xi[base + f] = A[f].y * s;
    }
}

// ---------------- K/V GEMM in frequency domain --------------------------------
__global__ __launch_bounds__(256) void k_gemm_kv(const float* __restrict__ WK,
                                                 const float* __restrict__ WV,
                                                 const float* __restrict__ bK,
                                                 const float* __restrict__ bV) {
    __shared__ float As[16][68];
    __shared__ float Bs[16][68];
    int ft = blockIdx.x;
    int mt = blockIdx.y;
    int bz = blockIdx.z;
    int b = bz >> 1, plane = bz & 1;
    const float* X = (plane ? g_Xi : g_Xr) + (size_t)b * CH * FPAD;
    int tid = threadIdx.x;
    int ty = tid >> 4, tx = tid & 15;
    int f0 = ft * 64, m0 = mt * 64;
    float acc[4][4] = {};
    for (int k0 = 0; k0 < 128; k0 += 16) {
        for (int l = tid; l < 1024; l += 256) {
            int m = l >> 4, k = l & 15;
            int gm = m0 + m;
            const float* W = (gm < 128) ? WK : WV;
            As[k][m] = W[(gm & 127) * 128 + k0 + k];
        }
        for (int l = tid; l < 1024; l += 256) {
            int k = l >> 6, f = l & 63;
            int gf = f0 + f;
            Bs[k][f] = (gf < NF) ? X[(size_t)(k0 + k) * FPAD + gf] : 0.f;
        }
        __syncthreads();
#pragma unroll
        for (int kk = 0; kk < 16; kk++) {
            float a[4], bb[4];
#pragma unroll
            for (int i = 0; i < 4; i++) a[i] = As[kk][ty + 16 * i];
#pragma unroll
            for (int j = 0; j < 4; j++) bb[j] = Bs[kk][tx + 16 * j];
#pragma unroll
            for (int i = 0; i < 4; i++)
#pragma unroll
                for (int j = 0; j < 4; j++) acc[i][j] += a[i] * bb[j];
        }
        __syncthreads();
    }
#pragma unroll
    for (int i = 0; i < 4; i++) {
        int gm = m0 + ty + 16 * i;
        float* outp;
        if (gm < 128) outp = plane ? g_Ki : g_Kr;
        else          outp = plane ? g_Vi : g_Vr;
        float bias = (gm < 128) ? bK[gm] : bV[gm - 128];
        size_t rb = (size_t)b * CH * FPAD + (size_t)(gm & 127) * FPAD;
#pragma unroll
        for (int j = 0; j < 4; j++) {
            int gf = f0 + tx + 16 * j;
            if (gf < NF) {
                float v = acc[i][j];
                if (plane == 0 && gf == 0) v += SQRTN * bias;
                outp[rb + gf] = v;
            }
        }
    }
}

// ---------------- fp32 [c][f] -> bf16 hi/lo [f][c] (transpose + split) --------
__global__ __launch_bounds__(256) void k_conv_qk() {
    __shared__ float ts[64][65];
    int ftile = blockIdx.x;            // 0..33
    int b = blockIdx.y >> 1;
    int ch0 = (blockIdx.y & 1) * 64;
    int w = blockIdx.z;                // 0..4
    const float* src;
    float sgn = 1.f;
    __nv_bfloat16 *dh, *dl;
    switch (w) {
        case 0:  src = g_Xr; dh = g_qrh; dl = g_qrl; break;
        case 1:  src = g_Xi; dh = g_qih; dl = g_qil; break;
        case 2:  src = g_Xi; sgn = -1.f; dh = g_qnh; dl = g_qnl; break;
        case 3:  src = g_Kr; dh = g_krh; dl = g_krl; break;
        default: src = g_Ki; dh = g_kih; dl = g_kil; break;
    }
    int f0 = ftile * 64;
    size_t sbase = (size_t)b * CH * FPAD;
    for (int idx = threadIdx.x; idx < 4096; idx += 256) {
        int c = idx >> 6, f = idx & 63;
        int gf = f0 + f;
        float v = (gf < NF) ? sgn * src[sbase + (size_t)(ch0 + c) * FPAD + gf] : 0.f;
        ts[f][c] = v;
    }
    __syncthreads();
    for (int idx = threadIdx.x; idx < 4096; idx += 256) {
        int f = idx >> 6, c = idx & 63;
        float v = ts[f][c];
        __nv_bfloat16 h = __float2bfloat16(v);
        size_t o = ((size_t)b * FT + f0 + f) * CH + ch0 + c;
        dh[o] = h;
        dl[o] = __float2bfloat16(v - __bfloat162float(h));
    }
}

// ---------------- fp32 V [c][f] -> bf16 hi/lo [c][g] (split, pad) -------------
__global__ __launch_bounds__(256) void k_conv_v() {
    int plane = blockIdx.y;
    size_t idx = (size_t)blockIdx.x * 256 + threadIdx.x;
    if (idx >= VN) return;
    int g = (int)(idx % FT);
    size_t bc = idx / FT;
    const float* src = plane ? g_Vi : g_Vr;
    float v = (g < NF) ? src[bc * FPAD + g] : 0.f;
    __nv_bfloat16 h = __float2bfloat16(v);
    __nv_bfloat16 l = __float2bfloat16(v - __bfloat162float(h));
    if (plane) { g_vih[idx] = h; g_vil[idx] = l; }
    else       { g_vrh[idx] = h; g_vrl[idx] = l; }
}

// ---------------- |QK^T| via tcgen05 ------------------------------------------
__global__ __launch_bounds__(256, 1) __cluster_dims__(1, 1, 1) void k_qk_mma() {
    extern __shared__ char sm[];
    uint32_t smb = smem_u32(sm);
    int tid = threadIdx.x, wid = tid >> 5, lane = tid & 31;
    int g0 = blockIdx.x * 128, f0 = blockIdx.y * 128, b = blockIdx.z;

    if (wid == 0) tc_alloc(smb + R_CTRL, 256);
    if (tid == 0) MBAR_INIT(smb + R_CTRL + 8, 1);
    __syncthreads();
    uint32_t tm;
    asm volatile("ld.shared.b32 %0, [%1];" : "=r"(tm) : "r"(smb + R_CTRL));
    uint32_t mbar = smb + R_CTRL + 8;

    size_t kb = ((size_t)b * FT + g0) * CH;
    load_tile_pair(sm, R_B0, g_krh, g_krl, kb, CH);
    load_tile_pair(sm, R_B1, g_kih, g_kil, kb, CH);
    size_t qb = ((size_t)b * FT + f0) * CH;
    load_tile_pair(sm, R_A, g_qrh, g_qrl, qb, CH);
    FENCE_ASYNC();
    __syncthreads();

    uint32_t phase = 0;
    if (wid == 0 && elect_one()) {
        mma_pair(tm, smb, R_A, R_B0, 1);        // Sr += Qr*Kr
        mma_pair(tm + 128, smb, R_A, R_B1, 1);  // Si += Qr*Ki
        tc_commit(mbar);
    }
    mbar_wait(mbar, phase); phase ^= 1;

    load_tile_pair(sm, R_A, g_qnh, g_qnl, qb, CH);
    FENCE_ASYNC();
    __syncthreads();
    if (wid == 0 && elect_one()) {
        mma_pair(tm, smb, R_A, R_B1, 0);        // Sr += (-Qi)*Ki
        tc_commit(mbar);
    }
    mbar_wait(mbar, phase); phase ^= 1;

    load_tile_pair(sm, R_A, g_qih, g_qil, qb, CH);
    FENCE_ASYNC();
    __syncthreads();
    if (wid == 0 && elect_one()) {
        mma_pair(tm + 128, smb, R_A, R_B0, 0);  // Si += Qi*Kr
        tc_commit(mbar);
    }
    mbar_wait(mbar, phase); phase ^= 1;
    tc_fence_after();

    // epilogue: warps 0-3 read Sr, 4-7 read Si; stage fp32; write |S|*scale
    {
        int half = wid >> 2, w4 = wid & 3;
        float* stage = (float*)(sm + (half ? STAGE1 : STAGE0));
        uint32_t dbase = tm + half * 128;
        int row = w4 * 32 + lane;
#pragma unroll
        for (int part = 0; part < 4; part++) {
            uint32_t r[32];
            tc_ld_x32(r, dbase + part * 32);
            tc_wait_ld();
#pragma unroll
            for (int c = 0; c < 32; c++) stage[row * 132 + part * 32 + c] = __uint_as_float(r[c]);
        }
    }
    __syncthreads();
    {
        const float* str = (const float*)(sm + STAGE0);
        const float* sti = (const float*)(sm + STAGE1);
        size_t sbase = ((size_t)b * FT + f0) * FT + g0;
        for (int idx = tid; idx < 128 * 128; idx += 256) {
            int row = idx >> 7, col = idx & 127;
            float sr = str[row * 132 + col], si = sti[row * 132 + col];
            g_S[sbase + (size_t)row * FT + col] = sqrtf(sr * sr + si * si) * ATT_SCALE;
        }
    }
    __syncthreads();
    if (tid == 0) MBAR_INVAL(mbar);
    __syncthreads();
    if (wid == 0) tc_dealloc(tm, 256);
}

// ---------------- row softmax -> P (bf16 hi/lo) --------------------------------
__global__ __launch_bounds__(256) void k_softmax() {
    __shared__ float red[8];
    __shared__ float bcv[2];
    int rowid = blockIdx.x;
    int b = rowid / NF, f = rowid - b * NF;
    const float* srow = g_S + ((size_t)b * FT + f) * FT;
    int tid = threadIdx.x, wid = tid >> 5, lane = tid & 31;
    float mx = -1e30f;
    for (int g = tid; g < NF; g += 256) mx = fmaxf(mx, srow[g]);
#pragma unroll
    for (int m = 16; m; m >>= 1) mx = fmaxf(mx, __shfl_xor_sync(0xffffffffu, mx, m));
    if (lane == 0) red[wid] = mx;
    __syncthreads();
    if (tid == 0) { float v = red[0]; for (int i = 1; i < 8; i++) v = fmaxf(v, red[i]); bcv[0] = v; }
    __syncthreads();
    float mxv = bcv[0];
    float sum = 0.f;
    for (int g = tid; g < NF; g += 256) sum += __expf(srow[g] - mxv);
#pragma unroll
    for (int m = 16; m; m >>= 1) sum += __shfl_xor_sync(0xffffffffu, sum, m);
    if (lane == 0) red[wid] = sum;
    __syncthreads();
    if (tid == 0) { float v = 0.f; for (int i = 0; i < 8; i++) v += red[i]; bcv[1] = v; }
    __syncthreads();
    float inv = 1.0f / bcv[1];
    size_t obase = ((size_t)b * FT + f) * FT;
    for (int g = tid; g < FT; g += 256) {
        float p = (g < NF) ? __expf(srow[g] - mxv) * inv : 0.f;
        __nv_bfloat16 h = __float2bfloat16(p);
        g_ph[obase + g] = h;
        g_pl[obase + g] = __float2bfloat16(p - __bfloat162float(h));
    }
}

// ---------------- O = P @ V via tcgen05 ----------------------------------------
__global__ __launch_bounds__(256, 1) __cluster_dims__(1, 1, 1) void k_av_mma() {
    extern __shared__ char sm[];
    uint32_t smb = smem_u32(sm);
    int tid = threadIdx.x, wid = tid >> 5, lane = tid & 31;
    int f0 = blockIdx.x * 128, b = blockIdx.y;
    if (wid == 0) tc_alloc(smb + R_CTRL, 256);
    if (tid == 0) MBAR_INIT(smb + R_CTRL + 8, 1);
    __syncthreads();
    uint32_t tm;
    asm volatile("ld.shared.b32 %0, [%1];" : "=r"(tm) : "r"(smb + R_CTRL));
    uint32_t mbar = smb + R_CTRL + 8;
    uint32_t phase = 0;
    for (int kt = 0; kt < 17; kt++) {
        int g0 = kt * 128;
        size_t pb = ((size_t)b * FT + f0) * FT + g0;
        load_tile_pair(sm, R_A, g_ph, g_pl, pb, FT);
        size_t vb = ((size_t)b * CH) * FT + g0;
        load_tile_pair(sm, R_B0, g_vrh, g_vrl, vb, FT);
        load_tile_pair(sm, R_B1, g_vih, g_vil, vb, FT);
        FENCE_ASYNC();
        __syncthreads();
        if (wid == 0 && elect_one()) {
            mma_pair(tm, smb, R_A, R_B0, kt == 0);        // Or += P*Vr
            mma_pair(tm + 128, smb, R_A, R_B1, kt == 0);  // Oi += P*Vi
            tc_commit(mbar);
        }
        mbar_wait(mbar, phase); phase ^= 1;
    }
    tc_fence_after();
    {
        int half = wid >> 2, w4 = wid & 3;
        float* stage = (float*)(sm + (half ? STAGE1 : STAGE0));
        uint32_t dbase = tm + half * 128;
        int row = w4 * 32 + lane;
#pragma unroll
        for (int part = 0; part < 4; part++) {
            uint32_t r[32];
            tc_ld_x32(r, dbase + part * 32);
            tc_wait_ld();
#pragma unroll
            for (int c = 0; c < 32; c++) stage[row * 132 + part * 32 + c] = __uint_as_float(r[c]);
        }
    }
    __syncthreads();
    {
        const float* str = (const float*)(sm + STAGE0);
        const float* sti = (const float*)(sm + STAGE1);
        for (int idx = tid; idx < 128 * 128; idx += 256) {
            int c = idx >> 7, fl = idx & 127;
            int gf = f0 + fl;
            if (gf < NF) {
                size_t o = ((size_t)b * CH + c) * FPAD + gf;
                g_Or[o] = str[fl * 132 + c];
                g_Oi[o] = sti[fl * 132 + c];
            }
        }
    }
    __syncthreads();
    if (tid == 0) MBAR_INVAL(mbar);
    __syncthreads();
    if (wid == 0) tc_dealloc(tm, 256);
}

// ---------------- energy / median / normalize / quantile / mask ----------------
__global__ __launch_bounds__(128) void k_energy() {
    int b = blockIdx.y;
    int f = blockIdx.x * 128 + threadIdx.x;
    if (f >= NF) return;
    size_t base = (size_t)b * CH * FPAD + f;
    float e = 0.f;
#pragma unroll 4
    for (int c = 0; c < 128; c++) {
        float r = g_Xr[base + (size_t)c * FPAD];
        float im = g_Xi[base + (size_t)c * FPAD];
        e += r * r + im * im;
    }
    g_energy[b * NF + f] = e;
}

__global__ __launch_bounds__(1024) void k_median() {
    __shared__ float s[4096];
    int b = blockIdx.x;
    for (int i = threadIdx.x; i < 4096; i += 1024) s[i] = (i < NF) ? g_energy[b * NF + i] : 1e30f;
    __syncthreads();
    for (int k = 2; k <= 4096; k <<= 1) {
        for (int j = k >> 1; j > 0; j >>= 1) {
            for (int i = threadIdx.x; i < 4096; i += 1024) {
                int ixj = i ^ j;
                if (ixj > i) {
                    bool up = ((i & k) == 0);
                    float a = s[i], bv = s[ixj];
                    if (up ? (a > bv) : (a < bv)) { s[i] = bv; s[ixj] = a; }
                }
            }
            __syncthreads();
        }
    }
    if (threadIdx.x == 0) g_med[b] = s[1024];
}

__global__ __launch_bounds__(256) void k_normalize() {
    int idx = blockIdx.x * 256 + threadIdx.x;
    if (idx >= BATCH * NF) return;
    int b = idx / NF;
    g_normv[idx] = g_energy[idx] / (g_med[b] + 1e-6f);
}

__global__ __launch_bounds__(1024) void k_quantile(const float* __restrict__ qparam) {
    extern __shared__ float s[];
    const int n = BATCH * NF;
    const int NP = 32768;
    for (int i = threadIdx.x; i < NP; i += 1024) s[i] = (i < n) ? g_normv[i] : 1e30f;
    __syncthreads();
    for (int k = 2; k <= NP; k <<= 1) {
        for (int j = k >> 1; j > 0; j >>= 1) {
            for (int i = threadIdx.x; i < NP; i += 1024) {
                int ixj = i ^ j;
                if (ixj > i) {
                    bool up = ((i & k) == 0);
                    float a = s[i], bv = s[ixj];
                    if (up ? (a > bv) : (a < bv)) { s[i] = bv; s[ixj] = a; }
                }
            }
            __syncthreads();
        }
    }
    if (threadIdx.x == 0) {
        float q = qparam[0];
        float pos = q * (float)(n - 1);
        int lo = (int)floorf(pos);
        if (lo < 0) lo = 0;
        if (lo > n - 2) lo = n - 2;
        float frac = pos - (float)lo;
        g_thr[0] = s[lo] + (s[lo + 1] - s[lo]) * frac;
    }
}

__global__ __launch_bounds__(256) void k_hifreq(const float* __restrict__ w_high) {
    int bc = blockIdx.x;
    int b = bc >> 7, c = bc & 127;
    float whr = w_high[c * 2], whi = w_high[c * 2 + 1];
    float t = g_thr[0];
    size_t base = (size_t)bc * FPAD;
    for (int f = threadIdx.x; f < NF; f += 256) {
        if (g_normv[b * NF + f] > t) {
            float xr = g_Xr[base + f], xi = g_Xi[base + f];
            g_Or[base + f] += xr * whr - xi * whi;
            g_Oi[base + f] += xr * whi + xi * whr;
        }
    }
}

// ---------------- inverse rfft -> output (B,C,N) ------------------------------
__global__ __launch_bounds__(512) void k_ifft(float* __restrict__ out) {
    extern __shared__ float2 sm2[];
    float2* A = sm2;
    float2* Bb = sm2 + 4096;
    int bc = blockIdx.x;
    size_t base = (size_t)bc * FPAD;
    for (int k = threadIdx.x; k < 4096; k += 512) {
        int kk = (k <= 2048) ? k : (4096 - k);
        float sgn = (k <= 2048) ? 1.f : -1.f;
        A[k] = make_float2(g_Or[base + kk], sgn * g_Oi[base + kk]);
    }
    fft4096<1>(A, Bb);
    const float s = 1.0f / SQRTN;
    float* orow = out + (size_t)bc * NT;
    for (int n = threadIdx.x; n < 4096; n += 512) orow[n] = A[n].x * s;
}

// ---------------- launch -------------------------------------------------------
extern "C" void kernel_launch(void* const* d_in, const int* in_sizes, int n_in,
                              void* d_out, int out_size) {
    const float* x_in   = (const float*)d_in[0];
    const float* W_K    = (const float*)d_in[1];
    const float* b_K    = (const float*)d_in[2];
    const float* W_V    = (const float*)d_in[3];
    const float* b_V    = (const float*)d_in[4];
    const float* w_high = (const float*)d_in[5];
    const float* qparam = (const float*)d_in[6];
    float* out = (float*)d_out;

    const int fft_smem = 2 * 4096 * sizeof(float2);
    const int qnt_smem = 32768 * sizeof(float);
    cudaFuncSetAttribute(k_fft_fwd,  cudaFuncAttributeMaxDynamicSharedMemorySize, fft_smem);
    cudaFuncSetAttribute(k_ifft,     cudaFuncAttributeMaxDynamicSharedMemorySize, fft_smem);
    cudaFuncSetAttribute(k_qk_mma,   cudaFuncAttributeMaxDynamicSharedMemorySize, MMA_SMEM_BYTES);
    cudaFuncSetAttribute(k_av_mma,   cudaFuncAttributeMaxDynamicSharedMemorySize, MMA_SMEM_BYTES);
    cudaFuncSetAttribute(k_quantile, cudaFuncAttributeMaxDynamicSharedMemorySize, qnt_smem);

    k_fft_fwd<<<BATCH * CH, 512, fft_smem>>>(x_in);
    k_gemm_kv<<<dim3(33, 4, 16), 256>>>(W_K, W_V, b_K, b_V);
    k_conv_qk<<<dim3(34, 16, 5), 256>>>();
    k_conv_v<<<dim3((unsigned)((VN + 255) / 256), 2), 256>>>();
    k_qk_mma<<<dim3(17, 17, 8), 256, MMA_SMEM_BYTES>>>();
    k_softmax<<<BATCH * NF, 256>>>();
    k_av_mma<<<dim3(17, 8), 256, MMA_SMEM_BYTES>>>();
    k_energy<<<dim3(17, BATCH), 128>>>();
    k_median<<<BATCH, 1024>>>();
    k_normalize<<<(BATCH * NF + 255) / 256, 256>>>();
    k_quantile<<<1, 1024, qnt_smem>>>(qparam);
    k_hifreq<<<BATCH * CH, 256>>>(w_high);
    k_ifft<<<BATCH * CH, 512, fft_smem>>>(out);
}

// round 4
// speedup vs baseline: 2.1059x; 1.0741x over previous
#include <cuda_runtime.h>
#include <cuda_bf16.h>
#include <math.h>
#include <stdint.h>

#define BATCH 8
#define CH    128
#define NT    4096
#define NF    2049
#define FPAD  2064
#define FT    2176          /* padded F for tensor path: 17*128 */
#define SQRTN 64.0f
#define ATT_SCALE 0.08838834764831845f  /* 1/sqrt(128) */

// tcgen05 PTX is only legal in the arch-specific (sm_103a) compile pass.
#if defined(__CUDA_ARCH_FEAT_SM103_ALL) || defined(__CUDA_ARCH_FEAT_SM100_ALL)
#define TC_ENABLED 1
#else
#define TC_ENABLED 0
#endif

// ---------------- scratch (device globals; no allocation in kernel_launch) ----
__device__ float g_Xr[BATCH*CH*FPAD];
__device__ float g_Xi[BATCH*CH*FPAD];
__device__ float g_Kr[BATCH*CH*FPAD];
__device__ float g_Ki[BATCH*CH*FPAD];
__device__ float g_Vr[BATCH*CH*FPAD];
__device__ float g_Vi[BATCH*CH*FPAD];
__device__ float g_Or[BATCH*CH*FPAD];
__device__ float g_Oi[BATCH*CH*FPAD];
__device__ float g_energy[BATCH*NF];
__device__ float g_normv[BATCH*NF];
__device__ float g_med[BATCH];
__device__ float g_thr[1];
__device__ float2 g_tw[4096];          /* FFT twiddle table */
__device__ float g_linv[BATCH*FT];     /* 1 / row-sum of exp */

// bf16 split planes for tensor cores
#define QKN ((size_t)BATCH*FT*CH)     /* [b][f][c] */
#define VN  ((size_t)BATCH*CH*FT)     /* [b][c][g] */
#define PN  ((size_t)BATCH*FT*FT)     /* [b][f][g] */
__device__ __align__(256) __nv_bfloat16 g_qrh[QKN], g_qrl[QKN];
__device__ __align__(256) __nv_bfloat16 g_qih[QKN], g_qil[QKN];
__device__ __align__(256) __nv_bfloat16 g_qnh[QKN], g_qnl[QKN];   /* -Qi */
__device__ __align__(256) __nv_bfloat16 g_krh[QKN], g_krl[QKN];
__device__ __align__(256) __nv_bfloat16 g_kih[QKN], g_kil[QKN];
__device__ __align__(256) __nv_bfloat16 g_vrh[VN],  g_vrl[VN];
__device__ __align__(256) __nv_bfloat16 g_vih[VN],  g_vil[VN];
__device__ __align__(256) float g_S[PN];   /* holds e = exp(|S|*scale) */

// ================= tcgen05 helpers (feature-gated) ============================
__device__ __forceinline__ uint32_t smem_u32(const void* p) {
    uint32_t a;
    asm("{ .reg .u64 t; cvta.to.shared.u64 t, %1; cvt.u32.u64 %0, t; }" : "=r"(a) : "l"(p));
    return a;
}
__device__ __forceinline__ uint32_t elect_one() {
    uint32_t p;
    asm volatile("{ .reg .pred p; elect.sync _|p, 0xFFFFFFFF; selp.b32 %0, 1, 0, p; }" : "=r"(p));
    return p;
}
__device__ __forceinline__ void tc_alloc(uint32_t sa, uint32_t n) {
#if TC_ENABLED
    asm volatile("tcgen05.alloc.cta_group::1.sync.aligned.shared::cta.b32 [%0], %1;" :: "r"(sa), "r"(n) : "memory");
#endif
}
__device__ __forceinline__ void tc_dealloc(uint32_t tm, uint32_t n) {
#if TC_ENABLED
    asm volatile("tcgen05.dealloc.cta_group::1.sync.aligned.b32 %0, %1;" :: "r"(tm), "r"(n));
#endif
}
__device__ __forceinline__ void tc_commit(uint32_t mb) {
#if TC_ENABLED
    asm volatile("tcgen05.commit.cta_group::1.mbarrier::arrive::one.shared::cluster.b64 [%0];" :: "r"(mb) : "memory");
#endif
}
__device__ __forceinline__ void tc_wait_ld() {
#if TC_ENABLED
    asm volatile("tcgen05.wait::ld.sync.aligned;" ::: "memory");
#endif
}
__device__ __forceinline__ void tc_fence_after() {
#if TC_ENABLED
    asm volatile("tcgen05.fence::after_thread_sync;" ::: "memory");
#endif
}
__device__ __forceinline__ void tc_ld_x32(uint32_t* r, uint32_t ta) {
#if TC_ENABLED
    asm volatile("tcgen05.ld.sync.aligned.32x32b.x32.b32 "
        "{%0, %1, %2, %3, %4, %5, %6, %7, %8, %9, %10, %11, %12, %13, %14, %15, "
        " %16, %17, %18, %19, %20, %21, %22, %23, %24, %25, %26, %27, %28, %29, %30, %31}, [%32];"
        : "=r"(r[0]),  "=r"(r[1]),  "=r"(r[2]),  "=r"(r[3]),
          "=r"(r[4]),  "=r"(r[5]),  "=r"(r[6]),  "=r"(r[7]),
          "=r"(r[8]),  "=r"(r[9]),  "=r"(r[10]), "=r"(r[11]),
          "=r"(r[12]), "=r"(r[13]), "=r"(r[14]), "=r"(r[15]),
          "=r"(r[16]), "=r"(r[17]), "=r"(r[18]), "=r"(r[19]),
          "=r"(r[20]), "=r"(r[21]), "=r"(r[22]), "=r"(r[23]),
          "=r"(r[24]), "=r"(r[25]), "=r"(r[26]), "=r"(r[27]),
          "=r"(r[28]), "=r"(r[29]), "=r"(r[30]), "=r"(r[31])
        : "r"(ta));
#else
    for (int i = 0; i < 32; i++) r[i] = 0u;
#endif
}

#define MBAR_INIT(mb, c)  asm volatile("mbarrier.init.shared.b64 [%0], %1;" :: "r"((uint32_t)(mb)), "r"((uint32_t)(c)) : "memory")
#define MBAR_INVAL(mb)    asm volatile("mbarrier.inval.shared.b64 [%0];" :: "r"((uint32_t)(mb)) : "memory")
__device__ __forceinline__ void mbar_wait(uint32_t mb, uint32_t ph) {
#if TC_ENABLED
    asm volatile("{\n\t.reg .pred P1;\n\tWL_%=:\n\t"
        "mbarrier.try_wait.parity.acquire.cta.shared::cta.b64 P1, [%0], %1, 0x989680;\n\t"
        "@P1 bra.uni WD_%=;\n\tbra.uni WL_%=;\n\tWD_%=:\n\t}"
        :: "r"(mb), "r"(ph) : "memory");
#endif
}
#define FENCE_ASYNC()     asm volatile("fence.proxy.async.shared::cta;" ::: "memory")

static constexpr uint64_t DESC_BASE_SW128 =
    (uint64_t(2) << 61) | (uint64_t(1) << 46) | (uint64_t(64) << 32) | (uint64_t(1) << 16);
#define MK_DESC(a) (DESC_BASE_SW128 | ((uint64_t)(((uint32_t)(a)) >> 4) & 0x3FFF))

// idesc kind::f16: F32 acc, BF16 a/b, K-major both, N=128, M=128
#define QK_IDESC ((1u<<4)|(1u<<7)|(1u<<10)|((128u/8u)<<17)|((128u/16u)<<24))

__device__ __forceinline__ void mma_f16_ss(uint32_t d, uint64_t ad, uint64_t bd, uint32_t idesc, int en) {
#if TC_ENABLED
    asm volatile("{\n\t.reg .pred p;\n\tsetp.ne.u32 p, %4, 0;\n\t"
        "tcgen05.mma.cta_group::1.kind::f16 [%0], %1, %2, %3, {%5, %5, %5, %5}, p;\n\t}"
        :: "r"(d), "l"(ad), "l"(bd), "r"(idesc), "r"((uint32_t)en), "r"(0u) : "memory");
#endif
}

// smem layout for both MMA kernels (bytes)
#define R_A    0
#define R_B0   65536
#define R_B1   131072
#define R_CTRL 196608
#define MMA_SMEM_BYTES (196608 + 16)
#define STAGE0 0
#define STAGE1 69632

// load 4 tiles (hi/lo × khalf) of [128 rows][64 bf16] with SW128 swizzle
__device__ __forceinline__ void load_tile_pair(char* sm, int region,
        const __nv_bfloat16* __restrict__ hi, const __nv_bfloat16* __restrict__ lo,
        size_t rbase, int rstride) {
    int t = threadIdx.x;
#pragma unroll
    for (int sp = 0; sp < 2; sp++) {
        const __nv_bfloat16* src = sp ? lo : hi;
#pragma unroll
        for (int kh = 0; kh < 2; kh++) {
#pragma unroll
            for (int i = 0; i < 4; i++) {
                int idx = t + i * 256;
                int row = idx >> 3, ch = idx & 7;
                uint4 v = *(const uint4*)(src + rbase + (size_t)row * rstride + kh * 64 + ch * 8);
                uint32_t off = (uint32_t)(row * 128 + ch * 16);
                off ^= (off >> 3) & 0x70;
                *(uint4*)(sm + region + (sp * 2 + kh) * 16384 + off) = v;
            }
        }
    }
}

// 3-chain split MMA: (hi,hi),(hi,lo),(lo,hi), K=128 = 2 khalves × 4 K16 steps
__device__ __forceinline__ void mma_pair(uint32_t d, uint32_t smb, int aoff, int boff, int first) {
    const int asp[3] = {0, 0, 1};
    const int bsp[3] = {0, 1, 0};
#pragma unroll
    for (int s = 0; s < 3; s++) {
#pragma unroll
        for (int kh = 0; kh < 2; kh++) {
            uint64_t ad = MK_DESC(smb + aoff + (asp[s] * 2 + kh) * 16384);
            uint64_t bd = MK_DESC(smb + boff + (bsp[s] * 2 + kh) * 16384);
#pragma unroll
            for (int ks = 0; ks < 4; ks++) {
                int en = !(first && s == 0 && kh == 0 && ks == 0);
                mma_f16_ss(d, ad + ks * 2, bd + ks * 2, QK_IDESC, en);
            }
        }
    }
}

// ---------------- twiddle table: tw[L+k] = (cos, sin)(pi*k/L) ------------------
__global__ __launch_bounds__(512) void k_twiddle() {
    for (int idx = threadIdx.x; idx < 4096; idx += 512) {
        if (idx == 0) { g_tw[0] = make_float2(1.f, 0.f); continue; }
        int s = 31 - __clz(idx);
        int L = 1 << s;
        int k = idx - L;
        float th = 3.14159265358979323846f * (float)k / (float)L;
        g_tw[idx] = make_float2(cosf(th), sinf(th));
    }
}

// ---------------- Stockham radix-2 FFT of 4096 in shared memory ---------------
// Twiddles read from smem table (no MUFU). SIGN = -1 fwd, +1 inv.
template <int SIGN>
__device__ __forceinline__ void fft4096(float2* bufA, float2* bufB, const float2* tws) {
    float2* src = bufA;
    float2* dst = bufB;
#pragma unroll 1
    for (int s = 0; s < 12; s++) {
        int L = 1 << s;
        __syncthreads();
        for (int i = threadIdx.x; i < 2048; i += 512) {
            int k = i & (L - 1);
            int j = i >> s;
            float2 u = src[i];
            float2 v = src[i + 2048];
            float2 t = tws[L + k];
            float cw = t.x, sw = (float)SIGN * t.y;
            float2 wv = make_float2(cw * v.x - sw * v.y, cw * v.y + sw * v.x);
            int o = (j << (s + 1)) + k;
            dst[o]     = make_float2(u.x + wv.x, u.y + wv.y);
            dst[o + L] = make_float2(u.x - wv.x, u.y - wv.y);
        }
        float2* t2 = src; src = dst; dst = t2;
    }
    __syncthreads();
}

#define FFT_SMEM (3 * 4096 * sizeof(float2))   /* A + B + twiddle table */

__global__ __launch_bounds__(512) void k_fft_fwd(const float* __restrict__ x_in) {
    extern __shared__ float2 sm2[];
    float2* A = sm2;
    float2* Bb = sm2 + 4096;
    float2* tws = sm2 + 8192;
    for (int i = threadIdx.x; i < 4096; i += 512) tws[i] = g_tw[i];
    int bc = blockIdx.x;
    const float* xrow = x_in + (size_t)bc * NT;
    for (int k = threadIdx.x; k < 4096; k += 512) A[k] = make_float2(xrow[k], 0.f);
    fft4096<-1>(A, Bb, tws);
    const float s = 1.0f / SQRTN;
    size_t base = (size_t)bc * FPAD;
    for (int f = threadIdx.x; f < NF; f += 512) {
        g_Xr[base + f] = A[f].x * s;
        g_Xi[base + f] = A[f].y * s;
    }
}

// ---------------- K/V GEMM in frequency domain --------------------------------
__global__ __launch_bounds__(256) void k_gemm_kv(const float* __restrict__ WK,
                                                 const float* __restrict__ WV,
                                                 const float* __restrict__ bK,
                                                 const float* __restrict__ bV) {
    __shared__ float As[16][68];
    __shared__ float Bs[16][68];
    int ft = blockIdx.x;
    int mt = blockIdx.y;
    int bz = blockIdx.z;
    int b = bz >> 1, plane = bz & 1;
    const float* X = (plane ? g_Xi : g_Xr) + (size_t)b * CH * FPAD;
    int tid = threadIdx.x;
    int ty = tid >> 4, tx = tid & 15;
    int f0 = ft * 64, m0 = mt * 64;
    float acc[4][4] = {};
    for (int k0 = 0; k0 < 128; k0 += 16) {
        for (int l = tid; l < 1024; l += 256) {
            int m = l >> 4, k = l & 15;
            int gm = m0 + m;
            const float* W = (gm < 128) ? WK : WV;
            As[k][m] = W[(gm & 127) * 128 + k0 + k];
        }
        for (int l = tid; l < 1024; l += 256) {
            int k = l >> 6, f = l & 63;
            int gf = f0 + f;
            Bs[k][f] = (gf < NF) ? X[(size_t)(k0 + k) * FPAD + gf] : 0.f;
        }
        __syncthreads();
#pragma unroll
        for (int kk = 0; kk < 16; kk++) {
            float a[4], bb[4];
#pragma unroll
            for (int i = 0; i < 4; i++) a[i] = As[kk][ty + 16 * i];
#pragma unroll
            for (int j = 0; j < 4; j++) bb[j] = Bs[kk][tx + 16 * j];
#pragma unroll
            for (int i = 0; i < 4; i++)
#pragma unroll
                for (int j = 0; j < 4; j++) acc[i][j] += a[i] * bb[j];
        }
        __syncthreads();
    }
#pragma unroll
    for (int i = 0; i < 4; i++) {
        int gm = m0 + ty + 16 * i;
        float* outp;
        if (gm < 128) outp = plane ? g_Ki : g_Kr;
        else          outp = plane ? g_Vi : g_Vr;
        float bias = (gm < 128) ? bK[gm] : bV[gm - 128];
        size_t rb = (size_t)b * CH * FPAD + (size_t)(gm & 127) * FPAD;
#pragma unroll
        for (int j = 0; j < 4; j++) {
            int gf = f0 + tx + 16 * j;
            if (gf < NF) {
                float v = acc[i][j];
                if (plane == 0 && gf == 0) v += SQRTN * bias;
                outp[rb + gf] = v;
            }
        }
    }
}

// ---------------- fp32 [c][f] -> bf16 hi/lo [f][c] (transpose + split) --------
__global__ __launch_bounds__(256) void k_conv_qk() {
    __shared__ float ts[64][65];
    int ftile = blockIdx.x;            // 0..33
    int b = blockIdx.y >> 1;
    int ch0 = (blockIdx.y & 1) * 64;
    int w = blockIdx.z;                // 0..4
    const float* src;
    float sgn = 1.f;
    __nv_bfloat16 *dh, *dl;
    switch (w) {
        case 0:  src = g_Xr; dh = g_qrh; dl = g_qrl; break;
        case 1:  src = g_Xi; dh = g_qih; dl = g_qil; break;
        case 2:  src = g_Xi; sgn = -1.f; dh = g_qnh; dl = g_qnl; break;
        case 3:  src = g_Kr; dh = g_krh; dl = g_krl; break;
        default: src = g_Ki; dh = g_kih; dl = g_kil; break;
    }
    int f0 = ftile * 64;
    size_t sbase = (size_t)b * CH * FPAD;
    for (int idx = threadIdx.x; idx < 4096; idx += 256) {
        int c = idx >> 6, f = idx & 63;
        int gf = f0 + f;
        float v = (gf < NF) ? sgn * src[sbase + (size_t)(ch0 + c) * FPAD + gf] : 0.f;
        ts[f][c] = v;
    }
    __syncthreads();
    for (int idx = threadIdx.x; idx < 4096; idx += 256) {
        int f = idx >> 6, c = idx & 63;
        float v = ts[f][c];
        __nv_bfloat16 h = __float2bfloat16(v);
        size_t o = ((size_t)b * FT + f0 + f) * CH + ch0 + c;
        dh[o] = h;
        dl[o] = __float2bfloat16(v - __bfloat162float(h));
    }
}

// ---------------- fp32 V [c][f] -> bf16 hi/lo [c][g] (split, pad) -------------
__global__ __launch_bounds__(256) void k_conv_v() {
    int plane = blockIdx.y;
    size_t idx = (size_t)blockIdx.x * 256 + threadIdx.x;
    if (idx >= VN) return;
    int g = (int)(idx % FT);
    size_t bc = idx / FT;
    const float* src = plane ? g_Vi : g_Vr;
    float v = (g < NF) ? src[bc * FPAD + g] : 0.f;
    __nv_bfloat16 h = __float2bfloat16(v);
    __nv_bfloat16 l = __float2bfloat16(v - __bfloat162float(h));
    if (plane) { g_vih[idx] = h; g_vil[idx] = l; }
    else       { g_vrh[idx] = h; g_vrl[idx] = l; }
}

// ---------------- QK^T via tcgen05, store e = exp(|S|*scale) ------------------
__global__ __launch_bounds__(256, 1) __cluster_dims__(1, 1, 1) void k_qk_mma() {
    extern __shared__ char sm[];
    uint32_t smb = smem_u32(sm);
    int tid = threadIdx.x, wid = tid >> 5, lane = tid & 31;
    int g0 = blockIdx.x * 128, f0 = blockIdx.y * 128, b = blockIdx.z;

    if (wid == 0) tc_alloc(smb + R_CTRL, 256);
    if (tid == 0) MBAR_INIT(smb + R_CTRL + 8, 1);
    __syncthreads();
    uint32_t tm;
    asm volatile("ld.shared.b32 %0, [%1];" : "=r"(tm) : "r"(smb + R_CTRL));
    uint32_t mbar = smb + R_CTRL + 8;

    size_t kb = ((size_t)b * FT + g0) * CH;
    load_tile_pair(sm, R_B0, g_krh, g_krl, kb, CH);
    load_tile_pair(sm, R_B1, g_kih, g_kil, kb, CH);
    size_t qb = ((size_t)b * FT + f0) * CH;
    load_tile_pair(sm, R_A, g_qrh, g_qrl, qb, CH);
    FENCE_ASYNC();
    __syncthreads();

    uint32_t phase = 0;
    if (wid == 0 && elect_one()) {
        mma_pair(tm, smb, R_A, R_B0, 1);        // Sr += Qr*Kr
        mma_pair(tm + 128, smb, R_A, R_B1, 1);  // Si += Qr*Ki
        tc_commit(mbar);
    }
    mbar_wait(mbar, phase); phase ^= 1;

    load_tile_pair(sm, R_A, g_qnh, g_qnl, qb, CH);
    FENCE_ASYNC();
    __syncthreads();
    if (wid == 0 && elect_one()) {
        mma_pair(tm, smb, R_A, R_B1, 0);        // Sr += (-Qi)*Ki
        tc_commit(mbar);
    }
    mbar_wait(mbar, phase); phase ^= 1;

    load_tile_pair(sm, R_A, g_qih, g_qil, qb, CH);
    FENCE_ASYNC();
    __syncthreads();
    if (wid == 0 && elect_one()) {
        mma_pair(tm + 128, smb, R_A, R_B0, 0);  // Si += Qi*Kr
        tc_commit(mbar);
    }
    mbar_wait(mbar, phase); phase ^= 1;
    tc_fence_after();

    // stage Sr (warps 0-3) and Si (warps 4-7) to smem fp32
    {
        int half = wid >> 2, w4 = wid & 3;
        float* stage = (float*)(sm + (half ? STAGE1 : STAGE0));
        uint32_t dbase = tm + half * 128;
        int row = w4 * 32 + lane;
#pragma unroll
        for (int part = 0; part < 4; part++) {
            uint32_t r[32];
            tc_ld_x32(r, dbase + part * 32);
            tc_wait_ld();
#pragma unroll
            for (int c = 0; c < 32; c++) stage[row * 132 + part * 32 + c] = __uint_as_float(r[c]);
        }
    }
    __syncthreads();
    // e = exp(scale * sqrt(sr^2+si^2)); sqrt via bit-seed Newton (FMA pipe, no MUFU)
    {
        const float* str = (const float*)(sm + STAGE0);
        const float* sti = (const float*)(sm + STAGE1);
        size_t sbase = ((size_t)b * FT + f0) * FT + g0;
        for (int idx = tid; idx < 128 * 128; idx += 256) {
            int row = idx >> 7, col = idx & 127;
            float sr = str[row * 132 + col], si = sti[row * 132 + col];
            float u = fmaxf(fmaf(sr, sr, si * si), 1e-30f);
            float y = __int_as_float(0x5f3759df - (__float_as_int(u) >> 1));
            float hu = 0.5f * u;
            y = y * (1.5f - hu * y * y);
            y = y * (1.5f - hu * y * y);
            float m = u * y;                         // ~sqrt(u), rel err ~4e-6
            float e = (g0 + col < NF) ? __expf(m * ATT_SCALE) : 0.f;
            g_S[sbase + (size_t)row * FT + col] = e;
        }
    }
    __syncthreads();
    if (tid == 0) MBAR_INVAL(mbar);
    __syncthreads();
    if (wid == 0) tc_dealloc(tm, 256);
}

// ---------------- per-row 1/sum(e) (deterministic) -----------------------------
__global__ __launch_bounds__(256) void k_rowsum() {
    int row = blockIdx.x * 8 + (threadIdx.x >> 5);   // [0, BATCH*FT)
    int lane = threadIdx.x & 31;
    const float4* p = (const float4*)(g_S + (size_t)row * FT);
    float s = 0.f;
    for (int i = lane; i < FT / 4; i += 32) {
        float4 v = p[i];
        s += (v.x + v.y) + (v.z + v.w);
    }
#pragma unroll
    for (int m = 16; m; m >>= 1) s += __shfl_xor_sync(0xffffffffu, s, m);
    if (lane == 0) g_linv[row] = (s > 0.f) ? 1.0f / s : 0.f;
}

// ---------------- O = P @ V via tcgen05; P built on-the-fly from e -------------
__global__ __launch_bounds__(256, 1) __cluster_dims__(1, 1, 1) void k_av_mma() {
    extern __shared__ char sm[];
    __shared__ float invl_s[128];
    uint32_t smb = smem_u32(sm);
    int tid = threadIdx.x, wid = tid >> 5, lane = tid & 31;
    int f0 = blockIdx.x * 128, b = blockIdx.y;
    if (wid == 0) tc_alloc(smb + R_CTRL, 256);
    if (tid == 0) MBAR_INIT(smb + R_CTRL + 8, 1);
    if (tid < 128) invl_s[tid] = g_linv[(size_t)b * FT + f0 + tid];
    __syncthreads();
    uint32_t tm;
    asm volatile("ld.shared.b32 %0, [%1];" : "=r"(tm) : "r"(smb + R_CTRL));
    uint32_t mbar = smb + R_CTRL + 8;
    uint32_t phase = 0;
    for (int kt = 0; kt < 17; kt++) {
        int g0 = kt * 128;
        // build A = P tile (bf16 hi/lo, swizzled) from e * invl
#pragma unroll
        for (int i = 0; i < 8; i++) {
            int chunk = tid + i * 256;               // 2048 chunks of 8 cols
            int row = chunk >> 4, c8 = (chunk & 15) * 8;
            const float* srow = g_S + ((size_t)b * FT + f0 + row) * FT + g0 + c8;
            float4 ea = *(const float4*)srow;
            float4 eb = *(const float4*)(srow + 4);
            float iv = invl_s[row];
            float pv[8] = {ea.x * iv, ea.y * iv, ea.z * iv, ea.w * iv,
                           eb.x * iv, eb.y * iv, eb.z * iv, eb.w * iv};
            uint32_t hiw[4], low[4];
#pragma unroll
            for (int j = 0; j < 4; j++) {
                __nv_bfloat162 h2 = __floats2bfloat162_rn(pv[2 * j], pv[2 * j + 1]);
                hiw[j] = *(uint32_t*)&h2;
                float l0 = pv[2 * j]     - __bfloat162float(__low2bfloat16(h2));
                float l1 = pv[2 * j + 1] - __bfloat162float(__high2bfloat16(h2));
                __nv_bfloat162 l2 = __floats2bfloat162_rn(l0, l1);
                low[j] = *(uint32_t*)&l2;
            }
            int kh = c8 >> 6;
            uint32_t off = (uint32_t)(row * 128 + (c8 & 63) * 2);
            off ^= (off >> 3) & 0x70;
            *(uint4*)(sm + R_A + kh * 16384 + off)       = make_uint4(hiw[0], hiw[1], hiw[2], hiw[3]);
            *(uint4*)(sm + R_A + (2 + kh) * 16384 + off) = make_uint4(low[0], low[1], low[2], low[3]);
        }
        size_t vb = ((size_t)b * CH) * FT + g0;
        load_tile_pair(sm, R_B0, g_vrh, g_vrl, vb, FT);
        load_tile_pair(sm, R_B1, g_vih, g_vil, vb, FT);
        FENCE_ASYNC();
        __syncthreads();
        if (wid == 0 && elect_one()) {
            mma_pair(tm, smb, R_A, R_B0, kt == 0);        // Or += P*Vr
            mma_pair(tm + 128, smb, R_A, R_B1, kt == 0);  // Oi += P*Vi
            tc_commit(mbar);
        }
        mbar_wait(mbar, phase); phase ^= 1;
    }
    tc_fence_after();
    {
        int half = wid >> 2, w4 = wid & 3;
        float* stage = (float*)(sm + (half ? STAGE1 : STAGE0));
        uint32_t dbase = tm + half * 128;
        int row = w4 * 32 + lane;
#pragma unroll
        for (int part = 0; part < 4; part++) {
            uint32_t r[32];
            tc_ld_x32(r, dbase + part * 32);
            tc_wait_ld();
#pragma unroll
            for (int c = 0; c < 32; c++) stage[row * 132 + part * 32 + c] = __uint_as_float(r[c]);
        }
    }
    __syncthreads();
    {
        const float* str = (const float*)(sm + STAGE0);
        const float* sti = (const float*)(sm + STAGE1);
        for (int idx = tid; idx < 128 * 128; idx += 256) {
            int c = idx >> 7, fl = idx & 127;
            int gf = f0 + fl;
            if (gf < NF) {
                size_t o = ((size_t)b * CH + c) * FPAD + gf;
                g_Or[o] = str[fl * 132 + c];
                g_Oi[o] = sti[fl * 132 + c];
            }
        }
    }
    __syncthreads();
    if (tid == 0) MBAR_INVAL(mbar);
    __syncthreads();
    if (wid == 0) tc_dealloc(tm, 256);
}

// ---------------- energy / median / normalize / quantile / mask ----------------
__global__ __launch_bounds__(128) void k_energy() {
    int b = blockIdx.y;
    int f = blockIdx.x * 128 + threadIdx.x;
    if (f >= NF) return;
    size_t base = (size_t)b * CH * FPAD + f;
    float e = 0.f;
#pragma unroll 4
    for (int c = 0; c < 128; c++) {
        float r = g_Xr[base + (size_t)c * FPAD];
        float im = g_Xi[base + (size_t)c * FPAD];
        e += r * r + im * im;
    }
    g_energy[b * NF + f] = e;
}

__global__ __launch_bounds__(1024) void k_median() {
    __shared__ float s[4096];
    int b = blockIdx.x;
    for (int i = threadIdx.x; i < 4096; i += 1024) s[i] = (i < NF) ? g_energy[b * NF + i] : 1e30f;
    __syncthreads();
    for (int k = 2; k <= 4096; k <<= 1) {
        for (int j = k >> 1; j > 0; j >>= 1) {
            for (int i = threadIdx.x; i < 4096; i += 1024) {
                int ixj = i ^ j;
                if (ixj > i) {
                    bool up = ((i & k) == 0);
                    float a = s[i], bv = s[ixj];
                    if (up ? (a > bv) : (a < bv)) { s[i] = bv; s[ixj] = a; }
                }
            }
            __syncthreads();
        }
    }
    if (threadIdx.x == 0) g_med[b] = s[1024];
}

__global__ __launch_bounds__(256) void k_normalize() {
    int idx = blockIdx.x * 256 + threadIdx.x;
    if (idx >= BATCH * NF) return;
    int b = idx / NF;
    g_normv[idx] = g_energy[idx] / (g_med[b] + 1e-6f);
}

__global__ __launch_bounds__(1024) void k_quantile(const float* __restrict__ qparam) {
    extern __shared__ float s[];
    const int n = BATCH * NF;
    const int NP = 32768;
    for (int i = threadIdx.x; i < NP; i += 1024) s[i] = (i < n) ? g_normv[i] : 1e30f;
    __syncthreads();
    for (int k = 2; k <= NP; k <<= 1) {
        for (int j = k >> 1; j > 0; j >>= 1) {
            for (int i = threadIdx.x; i < NP; i += 1024) {
                int ixj = i ^ j;
                if (ixj > i) {
                    bool up = ((i & k) == 0);
                    float a = s[i], bv = s[ixj];
                    if (up ? (a > bv) : (a < bv)) { s[i] = bv; s[ixj] = a; }
                }
            }
            __syncthreads();
        }
    }
    if (threadIdx.x == 0) {
        float q = qparam[0];
        float pos = q * (float)(n - 1);
        int lo = (int)floorf(pos);
        if (lo < 0) lo = 0;
        if (lo > n - 2) lo = n - 2;
        float frac = pos - (float)lo;
        g_thr[0] = s[lo] + (s[lo + 1] - s[lo]) * frac;
    }
}

__global__ __launch_bounds__(256) void k_hifreq(const float* __restrict__ w_high) {
    int bc = blockIdx.x;
    int b = bc >> 7, c = bc & 127;
    float whr = w_high[c * 2], whi = w_high[c * 2 + 1];
    float t = g_thr[0];
    size_t base = (size_t)bc * FPAD;
    for (int f = threadIdx.x; f < NF; f += 256) {
        if (g_normv[b * NF + f] > t) {
            float xr = g_Xr[base + f], xi = g_Xi[base + f];
            g_Or[base + f] += xr * whr - xi * whi;
            g_Oi[base + f] += xr * whi + xi * whr;
        }
    }
}

// ---------------- inverse rfft -> output (B,C,N) ------------------------------
__global__ __launch_bounds__(512) void k_ifft(float* __restrict__ out) {
    extern __shared__ float2 sm2[];
    float2* A = sm2;
    float2* Bb = sm2 + 4096;
    float2* tws = sm2 + 8192;
    for (int i = threadIdx.x; i < 4096; i += 512) tws[i] = g_tw[i];
    int bc = blockIdx.x;
    size_t base = (size_t)bc * FPAD;
    for (int k = threadIdx.x; k < 4096; k += 512) {
        int kk = (k <= 2048) ? k : (4096 - k);
        float sgn = (k <= 2048) ? 1.f : -1.f;
        A[k] = make_float2(g_Or[base + kk], sgn * g_Oi[base + kk]);
    }
    fft4096<1>(A, Bb, tws);
    const float s = 1.0f / SQRTN;
    float* orow = out + (size_t)bc * NT;
    for (int n = threadIdx.x; n < 4096; n += 512) orow[n] = A[n].x * s;
}

// ---------------- launch -------------------------------------------------------
extern "C" void kernel_launch(void* const* d_in, const int* in_sizes, int n_in,
                              void* d_out, int out_size) {
    const float* x_in   = (const float*)d_in[0];
    const float* W_K    = (const float*)d_in[1];
    const float* b_K    = (const float*)d_in[2];
    const float* W_V    = (const float*)d_in[3];
    const float* b_V    = (const float*)d_in[4];
    const float* w_high = (const float*)d_in[5];
    const float* qparam = (const float*)d_in[6];
    float* out = (float*)d_out;

    const int qnt_smem = 32768 * sizeof(float);
    cudaFuncSetAttribute(k_fft_fwd,  cudaFuncAttributeMaxDynamicSharedMemorySize, FFT_SMEM);
    cudaFuncSetAttribute(k_ifft,     cudaFuncAttributeMaxDynamicSharedMemorySize, FFT_SMEM);
    cudaFuncSetAttribute(k_qk_mma,   cudaFuncAttributeMaxDynamicSharedMemorySize, MMA_SMEM_BYTES);
    cudaFuncSetAttribute(k_av_mma,   cudaFuncAttributeMaxDynamicSharedMemorySize, MMA_SMEM_BYTES);
    cudaFuncSetAttribute(k_quantile, cudaFuncAttributeMaxDynamicSharedMemorySize, qnt_smem);

    k_twiddle<<<1, 512>>>();
    k_fft_fwd<<<BATCH * CH, 512, FFT_SMEM>>>(x_in);
    k_gemm_kv<<<dim3(33, 4, 16), 256>>>(W_K, W_V, b_K, b_V);
    k_conv_qk<<<dim3(34, 16, 5), 256>>>();
    k_conv_v<<<dim3((unsigned)((VN + 255) / 256), 2), 256>>>();
    k_qk_mma<<<dim3(17, 17, 8), 256, MMA_SMEM_BYTES>>>();
    k_rowsum<<<BATCH * FT / 8, 256>>>();
    k_av_mma<<<dim3(17, 8), 256, MMA_SMEM_BYTES>>>();
    k_energy<<<dim3(17, BATCH), 128>>>();
    k_median<<<BATCH, 1024>>>();
    k_normalize<<<(BATCH * NF + 255) / 256, 256>>>();
    k_quantile<<<1, 1024, qnt_smem>>>(qparam);
    k_hifreq<<<BATCH * CH, 256>>>(w_high);
    k_ifft<<<BATCH * CH, 512, FFT_SMEM>>>(out);
}

// round 5
// speedup vs baseline: 3.0708x; 1.4582x over previous
#include <cuda_runtime.h>
#include <cuda_bf16.h>
#include <math.h>
#include <stdint.h>

#define BATCH 8
#define CH    128
#define NT    4096
#define NF    2049
#define FPAD  2064
#define FT    2176          /* padded F for tensor path: 17*128 */
#define SQRTN 64.0f
#define ATT_SCALE 0.08838834764831845f  /* 1/sqrt(128) */

// tcgen05 PTX is only legal in the arch-specific (sm_103a) compile pass.
#if defined(__CUDA_ARCH_FEAT_SM103_ALL) || defined(__CUDA_ARCH_FEAT_SM100_ALL)
#define TC_ENABLED 1
#else
#define TC_ENABLED 0
#endif

// ---------------- scratch (device globals; no allocation in kernel_launch) ----
__device__ float g_Xr[BATCH*CH*FPAD];
__device__ float g_Xi[BATCH*CH*FPAD];
__device__ float g_Kr[BATCH*CH*FPAD];
__device__ float g_Ki[BATCH*CH*FPAD];
__device__ float g_Vr[BATCH*CH*FPAD];
__device__ float g_Vi[BATCH*CH*FPAD];
__device__ float g_Or[BATCH*CH*FPAD];
__device__ float g_Oi[BATCH*CH*FPAD];
__device__ float g_energy[BATCH*NF];
__device__ float g_normv[BATCH*NF];
__device__ float g_med[BATCH];
__device__ float g_thr[1];
__device__ float2 g_tw[4096];          /* FFT twiddle table */
__device__ float g_linv[BATCH*FT];     /* 1 / row-sum of exp */

// bf16 split planes for tensor cores
#define QKN ((size_t)BATCH*FT*CH)     /* [b][f][c] */
#define VN  ((size_t)BATCH*CH*FT)     /* [b][c][g] */
#define PN  ((size_t)BATCH*FT*FT)     /* [b][f][g] */
__device__ __align__(256) __nv_bfloat16 g_qrh[QKN], g_qrl[QKN];
__device__ __align__(256) __nv_bfloat16 g_qih[QKN], g_qil[QKN];
__device__ __align__(256) __nv_bfloat16 g_krh[QKN], g_krl[QKN];
__device__ __align__(256) __nv_bfloat16 g_kih[QKN], g_kil[QKN];
__device__ __align__(256) __nv_bfloat16 g_vrh[VN],  g_vrl[VN];
__device__ __align__(256) __nv_bfloat16 g_vih[VN],  g_vil[VN];
__device__ __align__(256) float g_S[PN];   /* holds e = exp(|S|*scale) */

// ================= tcgen05 helpers (feature-gated) ============================
__device__ __forceinline__ uint32_t smem_u32(const void* p) {
    uint32_t a;
    asm("{ .reg .u64 t; cvta.to.shared.u64 t, %1; cvt.u32.u64 %0, t; }" : "=r"(a) : "l"(p));
    return a;
}
__device__ __forceinline__ uint32_t elect_one() {
    uint32_t p;
    asm volatile("{ .reg .pred p; elect.sync _|p, 0xFFFFFFFF; selp.b32 %0, 1, 0, p; }" : "=r"(p));
    return p;
}
__device__ __forceinline__ void tc_alloc(uint32_t sa, uint32_t n) {
#if TC_ENABLED
    asm volatile("tcgen05.alloc.cta_group::1.sync.aligned.shared::cta.b32 [%0], %1;" :: "r"(sa), "r"(n) : "memory");
#endif
}
__device__ __forceinline__ void tc_dealloc(uint32_t tm, uint32_t n) {
#if TC_ENABLED
    asm volatile("tcgen05.dealloc.cta_group::1.sync.aligned.b32 %0, %1;" :: "r"(tm), "r"(n));
#endif
}
__device__ __forceinline__ void tc_commit(uint32_t mb) {
#if TC_ENABLED
    asm volatile("tcgen05.commit.cta_group::1.mbarrier::arrive::one.shared::cluster.b64 [%0];" :: "r"(mb) : "memory");
#endif
}
__device__ __forceinline__ void tc_wait_ld() {
#if TC_ENABLED
    asm volatile("tcgen05.wait::ld.sync.aligned;" ::: "memory");
#endif
}
__device__ __forceinline__ void tc_fence_after() {
#if TC_ENABLED
    asm volatile("tcgen05.fence::after_thread_sync;" ::: "memory");
#endif
}
__device__ __forceinline__ void tc_ld_x32(uint32_t* r, uint32_t ta) {
#if TC_ENABLED
    asm volatile("tcgen05.ld.sync.aligned.32x32b.x32.b32 "
        "{%0, %1, %2, %3, %4, %5, %6, %7, %8, %9, %10, %11, %12, %13, %14, %15, "
        " %16, %17, %18, %19, %20, %21, %22, %23, %24, %25, %26, %27, %28, %29, %30, %31}, [%32];"
        : "=r"(r[0]),  "=r"(r[1]),  "=r"(r[2]),  "=r"(r[3]),
          "=r"(r[4]),  "=r"(r[5]),  "=r"(r[6]),  "=r"(r[7]),
          "=r"(r[8]),  "=r"(r[9]),  "=r"(r[10]), "=r"(r[11]),
          "=r"(r[12]), "=r"(r[13]), "=r"(r[14]), "=r"(r[15]),
          "=r"(r[16]), "=r"(r[17]), "=r"(r[18]), "=r"(r[19]),
          "=r"(r[20]), "=r"(r[21]), "=r"(r[22]), "=r"(r[23]),
          "=r"(r[24]), "=r"(r[25]), "=r"(r[26]), "=r"(r[27]),
          "=r"(r[28]), "=r"(r[29]), "=r"(r[30]), "=r"(r[31])
        : "r"(ta));
#else
    for (int i = 0; i < 32; i++) r[i] = 0u;
#endif
}

#define MBAR_INIT(mb, c)  asm volatile("mbarrier.init.shared.b64 [%0], %1;" :: "r"((uint32_t)(mb)), "r"((uint32_t)(c)) : "memory")
#define MBAR_INVAL(mb)    asm volatile("mbarrier.inval.shared.b64 [%0];" :: "r"((uint32_t)(mb)) : "memory")
__device__ __forceinline__ void mbar_wait(uint32_t mb, uint32_t ph) {
#if TC_ENABLED
    asm volatile("{\n\t.reg .pred P1;\n\tWL_%=:\n\t"
        "mbarrier.try_wait.parity.acquire.cta.shared::cta.b64 P1, [%0], %1, 0x989680;\n\t"
        "@P1 bra.uni WD_%=;\n\tbra.uni WL_%=;\n\tWD_%=:\n\t}"
        :: "r"(mb), "r"(ph) : "memory");
#endif
}
#define FENCE_ASYNC()     asm volatile("fence.proxy.async.shared::cta;" ::: "memory")

static constexpr uint64_t DESC_BASE_SW128 =
    (uint64_t(2) << 61) | (uint64_t(1) << 46) | (uint64_t(64) << 32) | (uint64_t(1) << 16);
#define MK_DESC(a) (DESC_BASE_SW128 | ((uint64_t)(((uint32_t)(a)) >> 4) & 0x3FFF))

// idesc kind::f16: F32 acc, BF16 a/b, K-major both, N=128, M=128
#define QK_IDESC ((1u<<4)|(1u<<7)|(1u<<10)|((128u/8u)<<17)|((128u/16u)<<24))

__device__ __forceinline__ void mma_f16_ss(uint32_t d, uint64_t ad, uint64_t bd, uint32_t idesc, int en) {
#if TC_ENABLED
    asm volatile("{\n\t.reg .pred p;\n\tsetp.ne.u32 p, %4, 0;\n\t"
        "tcgen05.mma.cta_group::1.kind::f16 [%0], %1, %2, %3, {%5, %5, %5, %5}, p;\n\t}"
        :: "r"(d), "l"(ad), "l"(bd), "r"(idesc), "r"((uint32_t)en), "r"(0u) : "memory");
#endif
}

// smem layout for both MMA kernels (bytes)
#define R_A    0
#define R_B0   65536
#define R_B1   131072
#define R_CTRL 196608
#define MMA_SMEM_BYTES (196608 + 16)
#define STAGE0 0
#define STAGE1 69632

// load 4 tiles (hi/lo × khalf) of [128 rows][64 bf16] with SW128 swizzle
__device__ __forceinline__ void load_tile_pair(char* sm, int region,
        const __nv_bfloat16* __restrict__ hi, const __nv_bfloat16* __restrict__ lo,
        size_t rbase, int rstride) {
    int t = threadIdx.x;
#pragma unroll
    for (int sp = 0; sp < 2; sp++) {
        const __nv_bfloat16* src = sp ? lo : hi;
#pragma unroll
        for (int kh = 0; kh < 2; kh++) {
#pragma unroll
            for (int i = 0; i < 4; i++) {
                int idx = t + i * 256;
                int row = idx >> 3, ch = idx & 7;
                uint4 v = *(const uint4*)(src + rbase + (size_t)row * rstride + kh * 64 + ch * 8);
                uint32_t off = (uint32_t)(row * 128 + ch * 16);
                off ^= (off >> 3) & 0x70;
                *(uint4*)(sm + region + (sp * 2 + kh) * 16384 + off) = v;
            }
        }
    }
}

// 3-chain split MMA: (hi,hi),(hi,lo),(lo,hi), K=128 = 2 khalves × 4 K16 steps
__device__ __forceinline__ void mma_pair(uint32_t d, uint32_t smb, int aoff, int boff, int first) {
    const int asp[3] = {0, 0, 1};
    const int bsp[3] = {0, 1, 0};
#pragma unroll
    for (int s = 0; s < 3; s++) {
#pragma unroll
        for (int kh = 0; kh < 2; kh++) {
            uint64_t ad = MK_DESC(smb + aoff + (asp[s] * 2 + kh) * 16384);
            uint64_t bd = MK_DESC(smb + boff + (bsp[s] * 2 + kh) * 16384);
#pragma unroll
            for (int ks = 0; ks < 4; ks++) {
                int en = !(first && s == 0 && kh == 0 && ks == 0);
                mma_f16_ss(d, ad + ks * 2, bd + ks * 2, QK_IDESC, en);
            }
        }
    }
}

// ---------------- exact k-th order statistic via radix select -----------------
// sv: smem uint32 bits of NONNEGATIVE floats (monotone). Warp-aggregated hist.
__device__ __forceinline__ float radix_select_smem(const uint32_t* sv, int n, int k,
                                                   uint32_t* hist, int* sh, int nt) {
    int tid = threadIdx.x;
    int n_pad = ((n + nt - 1) / nt) * nt;
    uint32_t prefix = 0;
    int rank = k;
#pragma unroll 1
    for (int shift = 24; shift >= 0; shift -= 8) {
        for (int i = tid; i < 256; i += nt) hist[i] = 0;
        __syncthreads();
        uint32_t pmask = (shift == 24) ? 0u : (0xFFFFFFFFu << (shift + 8));
        for (int i = tid; i < n_pad; i += nt) {
            bool act = false;
            uint32_t bkt = 0x100u;
            if (i < n) {
                uint32_t v = sv[i];
                if ((v & pmask) == prefix) { act = true; bkt = (v >> shift) & 0xFFu; }
            }
            uint32_t grp = __match_any_sync(0xffffffffu, bkt);
            if (act) {
                int leader = __ffs(grp) - 1;
                if ((int)(tid & 31) == leader) atomicAdd(&hist[bkt], __popc(grp));
            }
        }
        __syncthreads();
        if (tid == 0) {
            int acc = 0, bsel = 255;
            for (int bkt = 0; bkt < 256; bkt++) {
                int c = (int)hist[bkt];
                if (acc + c > rank) { bsel = bkt; break; }
                acc += c;
            }
            sh[0] = bsel;
            sh[1] = rank - acc;
        }
        __syncthreads();
        prefix |= ((uint32_t)sh[0]) << shift;
        rank = sh[1];
        __syncthreads();
    }
    return __uint_as_float(prefix);
}

// ---------------- twiddle table: tw[L+k] = (cos, sin)(pi*k/L) ------------------
__global__ __launch_bounds__(512) void k_twiddle() {
    for (int idx = threadIdx.x; idx < 4096; idx += 512) {
        if (idx == 0) { g_tw[0] = make_float2(1.f, 0.f); continue; }
        int s = 31 - __clz(idx);
        int L = 1 << s;
        int k = idx - L;
        float th = 3.14159265358979323846f * (float)k / (float)L;
        g_tw[idx] = make_float2(cosf(th), sinf(th));
    }
}

// ---------------- Stockham radix-2 FFT of 4096 in shared memory ---------------
template <int SIGN>
__device__ __forceinline__ void fft4096(float2* bufA, float2* bufB, const float2* tws) {
    float2* src = bufA;
    float2* dst = bufB;
#pragma unroll 1
    for (int s = 0; s < 12; s++) {
        int L = 1 << s;
        __syncthreads();
        for (int i = threadIdx.x; i < 2048; i += 512) {
            int k = i & (L - 1);
            int j = i >> s;
            float2 u = src[i];
            float2 v = src[i + 2048];
            float2 t = tws[L + k];
            float cw = t.x, sw = (float)SIGN * t.y;
            float2 wv = make_float2(cw * v.x - sw * v.y, cw * v.y + sw * v.x);
            int o = (j << (s + 1)) + k;
            dst[o]     = make_float2(u.x + wv.x, u.y + wv.y);
            dst[o + L] = make_float2(u.x - wv.x, u.y - wv.y);
        }
        float2* t2 = src; src = dst; dst = t2;
    }
    __syncthreads();
}

#define FFT_SMEM (3 * 4096 * sizeof(float2))   /* A + B + twiddle table */

__global__ __launch_bounds__(512) void k_fft_fwd(const float* __restrict__ x_in) {
    extern __shared__ float2 sm2[];
    float2* A = sm2;
    float2* Bb = sm2 + 4096;
    float2* tws = sm2 + 8192;
    for (int i = threadIdx.x; i < 4096; i += 512) tws[i] = g_tw[i];
    int bc = blockIdx.x;
    const float* xrow = x_in + (size_t)bc * NT;
    for (int k = threadIdx.x; k < 4096; k += 512) A[k] = make_float2(xrow[k], 0.f);
    fft4096<-1>(A, Bb, tws);
    const float s = 1.0f / SQRTN;
    size_t base = (size_t)bc * FPAD;
    for (int f = threadIdx.x; f < NF; f += 512) {
        g_Xr[base + f] = A[f].x * s;
        g_Xi[base + f] = A[f].y * s;
    }
}

// ---------------- K/V GEMM in frequency domain --------------------------------
__global__ __launch_bounds__(256) void k_gemm_kv(const float* __restrict__ WK,
                                                 const float* __restrict__ WV,
                                                 const float* __restrict__ bK,
                                                 const float* __restrict__ bV) {
    __shared__ float As[16][68];
    __shared__ float Bs[16][68];
    int ft = blockIdx.x;
    int mt = blockIdx.y;
    int bz = blockIdx.z;
    int b = bz >> 1, plane = bz & 1;
    const float* X = (plane ? g_Xi : g_Xr) + (size_t)b * CH * FPAD;
    int tid = threadIdx.x;
    int ty = tid >> 4, tx = tid & 15;
    int f0 = ft * 64, m0 = mt * 64;
    float acc[4][4] = {};
    for (int k0 = 0; k0 < 128; k0 += 16) {
        for (int l = tid; l < 1024; l += 256) {
            int m = l >> 4, k = l & 15;
            int gm = m0 + m;
            const float* W = (gm < 128) ? WK : WV;
            As[k][m] = W[(gm & 127) * 128 + k0 + k];
        }
        for (int l = tid; l < 1024; l += 256) {
            int k = l >> 6, f = l & 63;
            int gf = f0 + f;
            Bs[k][f] = (gf < NF) ? X[(size_t)(k0 + k) * FPAD + gf] : 0.f;
        }
        __syncthreads();
#pragma unroll
        for (int kk = 0; kk < 16; kk++) {
            float a[4], bb[4];
#pragma unroll
            for (int i = 0; i < 4; i++) a[i] = As[kk][ty + 16 * i];
#pragma unroll
            for (int j = 0; j < 4; j++) bb[j] = Bs[kk][tx + 16 * j];
#pragma unroll
            for (int i = 0; i < 4; i++)
#pragma unroll
                for (int j = 0; j < 4; j++) acc[i][j] += a[i] * bb[j];
        }
        __syncthreads();
    }
#pragma unroll
    for (int i = 0; i < 4; i++) {
        int gm = m0 + ty + 16 * i;
        float* outp;
        if (gm < 128) outp = plane ? g_Ki : g_Kr;
        else          outp = plane ? g_Vi : g_Vr;
        float bias = (gm < 128) ? bK[gm] : bV[gm - 128];
        size_t rb = (size_t)b * CH * FPAD + (size_t)(gm & 127) * FPAD;
#pragma unroll
        for (int j = 0; j < 4; j++) {
            int gf = f0 + tx + 16 * j;
            if (gf < NF) {
                float v = acc[i][j];
                if (plane == 0 && gf == 0) v += SQRTN * bias;
                outp[rb + gf] = v;
            }
        }
    }
}

// ---------------- fp32 [c][f] -> bf16 hi/lo [f][c] (transpose + split) --------
__global__ __launch_bounds__(256) void k_conv_qk() {
    __shared__ float ts[64][65];
    int ftile = blockIdx.x;            // 0..33
    int b = blockIdx.y >> 1;
    int ch0 = (blockIdx.y & 1) * 64;
    int w = blockIdx.z;                // 0..3
    const float* src;
    __nv_bfloat16 *dh, *dl;
    switch (w) {
        case 0:  src = g_Xr; dh = g_qrh; dl = g_qrl; break;
        case 1:  src = g_Xi; dh = g_qih; dl = g_qil; break;
        case 2:  src = g_Kr; dh = g_krh; dl = g_krl; break;
        default: src = g_Ki; dh = g_kih; dl = g_kil; break;
    }
    int f0 = ftile * 64;
    size_t sbase = (size_t)b * CH * FPAD;
    for (int idx = threadIdx.x; idx < 4096; idx += 256) {
        int c = idx >> 6, f = idx & 63;
        int gf = f0 + f;
        float v = (gf < NF) ? src[sbase + (size_t)(ch0 + c) * FPAD + gf] : 0.f;
        ts[f][c] = v;
    }
    __syncthreads();
    for (int idx = threadIdx.x; idx < 4096; idx += 256) {
        int f = idx >> 6, c = idx & 63;
        float v = ts[f][c];
        __nv_bfloat16 h = __float2bfloat16(v);
        size_t o = ((size_t)b * FT + f0 + f) * CH + ch0 + c;
        dh[o] = h;
        dl[o] = __float2bfloat16(v - __bfloat162float(h));
    }
}

// ---------------- fp32 V [c][f] -> bf16 hi/lo [c][g] (split, pad) -------------
__global__ __launch_bounds__(256) void k_conv_v() {
    int plane = blockIdx.y;
    size_t idx = (size_t)blockIdx.x * 256 + threadIdx.x;
    if (idx >= VN) return;
    int g = (int)(idx % FT);
    size_t bc = idx / FT;
    const float* src = plane ? g_Vi : g_Vr;
    float v = (g < NF) ? src[bc * FPAD + g] : 0.f;
    __nv_bfloat16 h = __float2bfloat16(v);
    __nv_bfloat16 l = __float2bfloat16(v - __bfloat162float(h));
    if (plane) { g_vih[idx] = h; g_vil[idx] = l; }
    else       { g_vrh[idx] = h; g_vrl[idx] = l; }
}

// ---------------- QK^T via tcgen05 (4 accumulators), store e = exp(|S|*scale) --
__global__ __launch_bounds__(256, 1) __cluster_dims__(1, 1, 1) void k_qk_mma() {
    extern __shared__ char sm[];
    uint32_t smb = smem_u32(sm);
    int tid = threadIdx.x, wid = tid >> 5, lane = tid & 31;
    int g0 = blockIdx.x * 128, f0 = blockIdx.y * 128, b = blockIdx.z;

    if (wid == 0) tc_alloc(smb + R_CTRL, 512);
    if (tid == 0) MBAR_INIT(smb + R_CTRL + 8, 1);
    __syncthreads();
    uint32_t tm;
    asm volatile("ld.shared.b32 %0, [%1];" : "=r"(tm) : "r"(smb + R_CTRL));
    uint32_t mbar = smb + R_CTRL + 8;

    size_t kb = ((size_t)b * FT + g0) * CH;
    load_tile_pair(sm, R_B0, g_krh, g_krl, kb, CH);
    load_tile_pair(sm, R_B1, g_kih, g_kil, kb, CH);
    size_t qb = ((size_t)b * FT + f0) * CH;
    load_tile_pair(sm, R_A, g_qrh, g_qrl, qb, CH);
    FENCE_ASYNC();
    __syncthreads();

    uint32_t phase = 0;
    if (wid == 0 && elect_one()) {
        mma_pair(tm, smb, R_A, R_B0, 1);        // D0 = Qr*Kr
        mma_pair(tm + 128, smb, R_A, R_B1, 1);  // D1 = Qr*Ki
        tc_commit(mbar);
    }
    mbar_wait(mbar, phase); phase ^= 1;

    load_tile_pair(sm, R_A, g_qih, g_qil, qb, CH);
    FENCE_ASYNC();
    __syncthreads();
    if (wid == 0 && elect_one()) {
        mma_pair(tm + 256, smb, R_A, R_B1, 1);  // D2 = Qi*Ki
        mma_pair(tm + 384, smb, R_A, R_B0, 1);  // D3 = Qi*Kr
        tc_commit(mbar);
    }
    mbar_wait(mbar, phase); phase ^= 1;
    tc_fence_after();

    // warps 0-3: sr = D0 - D2 -> STAGE0; warps 4-7: si = D1 + D3 -> STAGE1
    {
        int half = wid >> 2, w4 = wid & 3;
        float* stage = (float*)(sm + (half ? STAGE1 : STAGE0));
        uint32_t dA = tm + (half ? 128 : 0);
        uint32_t dB = tm + (half ? 384 : 256);
        int row = w4 * 32 + lane;
#pragma unroll
        for (int part = 0; part < 4; part++) {
            uint32_t ra[32], rb[32];
            tc_ld_x32(ra, dA + part * 32);
            tc_ld_x32(rb, dB + part * 32);
            tc_wait_ld();
#pragma unroll
            for (int c = 0; c < 32; c++) {
                float fa = __uint_as_float(ra[c]);
                float fb = __uint_as_float(rb[c]);
                stage[row * 132 + part * 32 + c] = half ? (fa + fb) : (fa - fb);
            }
        }
    }
    __syncthreads();
    // e = exp(scale * sqrt(sr^2+si^2)); sqrt via bit-seed Newton (FMA pipe)
    {
        const float* str = (const float*)(sm + STAGE0);
        const float* sti = (const float*)(sm + STAGE1);
        size_t sbase = ((size_t)b * FT + f0) * FT + g0;
        for (int idx = tid; idx < 128 * 128; idx += 256) {
            int row = idx >> 7, col = idx & 127;
            float sr = str[row * 132 + col], si = sti[row * 132 + col];
            float u = fmaxf(fmaf(sr, sr, si * si), 1e-30f);
            float y = __int_as_float(0x5f3759df - (__float_as_int(u) >> 1));
            float hu = 0.5f * u;
            y = y * (1.5f - hu * y * y);
            y = y * (1.5f - hu * y * y);
            float m = u * y;                         // ~sqrt(u), rel err ~4e-6
            float e = (g0 + col < NF) ? __expf(m * ATT_SCALE) : 0.f;
            g_S[sbase + (size_t)row * FT + col] = e;
        }
    }
    __syncthreads();
    if (tid == 0) MBAR_INVAL(mbar);
    __syncthreads();
    if (wid == 0) tc_dealloc(tm, 512);
}

// ---------------- per-row 1/sum(e) (deterministic) -----------------------------
__global__ __launch_bounds__(256) void k_rowsum() {
    int row = blockIdx.x * 8 + (threadIdx.x >> 5);   // [0, BATCH*FT)
    int lane = threadIdx.x & 31;
    const float4* p = (const float4*)(g_S + (size_t)row * FT);
    float s = 0.f;
    for (int i = lane; i < FT / 4; i += 32) {
        float4 v = p[i];
        s += (v.x + v.y) + (v.z + v.w);
    }
#pragma unroll
    for (int m = 16; m; m >>= 1) s += __shfl_xor_sync(0xffffffffu, s, m);
    if (lane == 0) g_linv[row] = (s > 0.f) ? 1.0f / s : 0.f;
}

// ---------------- O = P @ V via tcgen05; P built on-the-fly from e -------------
__global__ __launch_bounds__(256, 1) __cluster_dims__(1, 1, 1) void k_av_mma() {
    extern __shared__ char sm[];
    __shared__ float invl_s[128];
    uint32_t smb = smem_u32(sm);
    int tid = threadIdx.x, wid = tid >> 5, lane = tid & 31;
    int f0 = blockIdx.x * 128, b = blockIdx.y;
    if (wid == 0) tc_alloc(smb + R_CTRL, 256);
    if (tid == 0) MBAR_INIT(smb + R_CTRL + 8, 1);
    if (tid < 128) invl_s[tid] = g_linv[(size_t)b * FT + f0 + tid];
    __syncthreads();
    uint32_t tm;
    asm volatile("ld.shared.b32 %0, [%1];" : "=r"(tm) : "r"(smb + R_CTRL));
    uint32_t mbar = smb + R_CTRL + 8;
    uint32_t phase = 0;
    for (int kt = 0; kt < 17; kt++) {
        int g0 = kt * 128;
        // build A = P tile (bf16 hi/lo, swizzled) from e * invl
#pragma unroll
        for (int i = 0; i < 8; i++) {
            int chunk = tid + i * 256;               // 2048 chunks of 8 cols
            int row = chunk >> 4, c8 = (chunk & 15) * 8;
            const float* srow = g_S + ((size_t)b * FT + f0 + row) * FT + g0 + c8;
            float4 ea = *(const float4*)srow;
            float4 eb = *(const float4*)(srow + 4);
            float iv = invl_s[row];
            float pv[8] = {ea.x * iv, ea.y * iv, ea.z * iv, ea.w * iv,
                           eb.x * iv, eb.y * iv, eb.z * iv, eb.w * iv};
            uint32_t hiw[4], low[4];
#pragma unroll
            for (int j = 0; j < 4; j++) {
                __nv_bfloat162 h2 = __floats2bfloat162_rn(pv[2 * j], pv[2 * j + 1]);
                hiw[j] = *(uint32_t*)&h2;
                float l0 = pv[2 * j]     - __bfloat162float(__low2bfloat16(h2));
                float l1 = pv[2 * j + 1] - __bfloat162float(__high2bfloat16(h2));
                __nv_bfloat162 l2 = __floats2bfloat162_rn(l0, l1);
                low[j] = *(uint32_t*)&l2;
            }
            int kh = c8 >> 6;
            uint32_t off = (uint32_t)(row * 128 + (c8 & 63) * 2);
            off ^= (off >> 3) & 0x70;
            *(uint4*)(sm + R_A + kh * 16384 + off)       = make_uint4(hiw[0], hiw[1], hiw[2], hiw[3]);
            *(uint4*)(sm + R_A + (2 + kh) * 16384 + off) = make_uint4(low[0], low[1], low[2], low[3]);
        }
        size_t vb = ((size_t)b * CH) * FT + g0;
        load_tile_pair(sm, R_B0, g_vrh, g_vrl, vb, FT);
        load_tile_pair(sm, R_B1, g_vih, g_vil, vb, FT);
        FENCE_ASYNC();
        __syncthreads();
        if (wid == 0 && elect_one()) {
            mma_pair(tm, smb, R_A, R_B0, kt == 0);        // Or += P*Vr
            mma_pair(tm + 128, smb, R_A, R_B1, kt == 0);  // Oi += P*Vi
            tc_commit(mbar);
        }
        mbar_wait(mbar, phase); phase ^= 1;
    }
    tc_fence_after();
    {
        int half = wid >> 2, w4 = wid & 3;
        float* stage = (float*)(sm + (half ? STAGE1 : STAGE0));
        uint32_t dbase = tm + half * 128;
        int row = w4 * 32 + lane;
#pragma unroll
        for (int part = 0; part < 4; part++) {
            uint32_t r[32];
            tc_ld_x32(r, dbase + part * 32);
            tc_wait_ld();
#pragma unroll
            for (int c = 0; c < 32; c++) stage[row * 132 + part * 32 + c] = __uint_as_float(r[c]);
        }
    }
    __syncthreads();
    {
        const float* str = (const float*)(sm + STAGE0);
        const float* sti = (const float*)(sm + STAGE1);
        for (int idx = tid; idx < 128 * 128; idx += 256) {
            int c = idx >> 7, fl = idx & 127;
            int gf = f0 + fl;
            if (gf < NF) {
                size_t o = ((size_t)b * CH + c) * FPAD + gf;
                g_Or[o] = str[fl * 132 + c];
                g_Oi[o] = sti[fl * 132 + c];
            }
        }
    }
    __syncthreads();
    if (tid == 0) MBAR_INVAL(mbar);
    __syncthreads();
    if (wid == 0) tc_dealloc(tm, 256);
}

// ---------------- energy / median / normalize / quantile / mask ----------------
__global__ __launch_bounds__(128) void k_energy() {
    int b = blockIdx.y;
    int f = blockIdx.x * 128 + threadIdx.x;
    if (f >= NF) return;
    size_t base = (size_t)b * CH * FPAD + f;
    float e = 0.f;
#pragma unroll 4
    for (int c = 0; c < 128; c++) {
        float r = g_Xr[base + (size_t)c * FPAD];
        float im = g_Xi[base + (size_t)c * FPAD];
        e += r * r + im * im;
    }
    g_energy[b * NF + f] = e;
}

// median of NF energies per batch = exact 1024-th order statistic (radix select)
__global__ __launch_bounds__(256) void k_median() {
    __shared__ uint32_t sv[NF];
    __shared__ uint32_t hist[256];
    __shared__ int sh[2];
    int b = blockIdx.x;
    for (int i = threadIdx.x; i < NF; i += 256) sv[i] = __float_as_uint(g_energy[b * NF + i]);
    __syncthreads();
    float m = radix_select_smem(sv, NF, NF / 2, hist, sh, 256);
    if (threadIdx.x == 0) g_med[b] = m;
}

__global__ __launch_bounds__(256) void k_normalize() {
    int idx = blockIdx.x * 256 + threadIdx.x;
    if (idx >= BATCH * NF) return;
    int b = idx / NF;
    g_normv[idx] = g_energy[idx] / (g_med[b] + 1e-6f);
}

// global quantile via exact radix select of k-th and (k+1)-th order statistics
#define QSEL_N (BATCH * NF)
#define QSEL_SMEM ((QSEL_N + 256 + 2) * 4)
__global__ __launch_bounds__(512) void k_quantile(const float* __restrict__ qparam) {
    extern __shared__ uint32_t qsm[];
    uint32_t* sv = qsm;
    uint32_t* hist = qsm + QSEL_N;
    int* sh = (int*)(hist + 256);
    for (int i = threadIdx.x; i < QSEL_N; i += 512) sv[i] = __float_as_uint(g_normv[i]);
    __syncthreads();
    float q = qparam[0];
    float pos = q * (float)(QSEL_N - 1);
    int lo = (int)floorf(pos);
    if (lo < 0) lo = 0;
    if (lo > QSEL_N - 2) lo = QSEL_N - 2;
    float frac = pos - (float)lo;
    float a = radix_select_smem(sv, QSEL_N, lo, hist, sh, 512);
    __syncthreads();
    float bb = radix_select_smem(sv, QSEL_N, lo + 1, hist, sh, 512);
    if (threadIdx.x == 0) g_thr[0] = a + (bb - a) * frac;
}

__global__ __launch_bounds__(256) void k_hifreq(const float* __restrict__ w_high) {
    int bc = blockIdx.x;
    int b = bc >> 7, c = bc & 127;
    float whr = w_high[c * 2], whi = w_high[c * 2 + 1];
    float t = g_thr[0];
    size_t base = (size_t)bc * FPAD;
    for (int f = threadIdx.x; f < NF; f += 256) {
        if (g_normv[b * NF + f] > t) {
            float xr = g_Xr[base + f], xi = g_Xi[base + f];
            g_Or[base + f] += xr * whr - xi * whi;
            g_Oi[base + f] += xr * whi + xi * whr;
        }
    }
}

// ---------------- inverse rfft -> output (B,C,N) ------------------------------
__global__ __launch_bounds__(512) void k_ifft(float* __restrict__ out) {
    extern __shared__ float2 sm2[];
    float2* A = sm2;
    float2* Bb = sm2 + 4096;
    float2* tws = sm2 + 8192;
    for (int i = threadIdx.x; i < 4096; i += 512) tws[i] = g_tw[i];
    int bc = blockIdx.x;
    size_t base = (size_t)bc * FPAD;
    for (int k = threadIdx.x; k < 4096; k += 512) {
        int kk = (k <= 2048) ? k : (4096 - k);
        float sgn = (k <= 2048) ? 1.f : -1.f;
        A[k] = make_float2(g_Or[base + kk], sgn * g_Oi[base + kk]);
    }
    fft4096<1>(A, Bb, tws);
    const float s = 1.0f / SQRTN;
    float* orow = out + (size_t)bc * NT;
    for (int n = threadIdx.x; n < 4096; n += 512) orow[n] = A[n].x * s;
}

// ---------------- launch -------------------------------------------------------
extern "C" void kernel_launch(void* const* d_in, const int* in_sizes, int n_in,
                              void* d_out, int out_size) {
    const float* x_in   = (const float*)d_in[0];
    const float* W_K    = (const float*)d_in[1];
    const float* b_K    = (const float*)d_in[2];
    const float* W_V    = (const float*)d_in[3];
    const float* b_V    = (const float*)d_in[4];
    const float* w_high = (const float*)d_in[5];
    const float* qparam = (const float*)d_in[6];
    float* out = (float*)d_out;

    cudaFuncSetAttribute(k_fft_fwd,  cudaFuncAttributeMaxDynamicSharedMemorySize, FFT_SMEM);
    cudaFuncSetAttribute(k_ifft,     cudaFuncAttributeMaxDynamicSharedMemorySize, FFT_SMEM);
    cudaFuncSetAttribute(k_qk_mma,   cudaFuncAttributeMaxDynamicSharedMemorySize, MMA_SMEM_BYTES);
    cudaFuncSetAttribute(k_av_mma,   cudaFuncAttributeMaxDynamicSharedMemorySize, MMA_SMEM_BYTES);
    cudaFuncSetAttribute(k_quantile, cudaFuncAttributeMaxDynamicSharedMemorySize, QSEL_SMEM);

    k_twiddle<<<1, 512>>>();
    k_fft_fwd<<<BATCH * CH, 512, FFT_SMEM>>>(x_in);
    k_gemm_kv<<<dim3(33, 4, 16), 256>>>(W_K, W_V, b_K, b_V);
    k_conv_qk<<<dim3(34, 16, 4), 256>>>();
    k_conv_v<<<dim3((unsigned)((VN + 255) / 256), 2), 256>>>();
    k_qk_mma<<<dim3(17, 17, 8), 256, MMA_SMEM_BYTES>>>();
    k_rowsum<<<BATCH * FT / 8, 256>>>();
    k_av_mma<<<dim3(17, 8), 256, MMA_SMEM_BYTES>>>();
    k_energy<<<dim3(17, BATCH), 128>>>();
    k_median<<<BATCH, 256>>>();
    k_normalize<<<(BATCH * NF + 255) / 256, 256>>>();
    k_quantile<<<1, 512, QSEL_SMEM>>>(qparam);
    k_hifreq<<<BATCH * CH, 256>>>(w_high);
    k_ifft<<<BATCH * CH, 512, FFT_SMEM>>>(out);
}

// round 8
// speedup vs baseline: 3.2980x; 1.0740x over previous
#include <cuda_runtime.h>
#include <cuda_bf16.h>
#include <math.h>
#include <stdint.h>

#define BATCH 8
#define CH    128
#define NT    4096
#define NF    2049
#define FPAD  2064
#define FT    2176          /* padded F for tensor path: 17*128 */
#define SQRTN 64.0f
#define ATT_SCALE 0.08838834764831845f  /* 1/sqrt(128) */

#if defined(__CUDA_ARCH_FEAT_SM103_ALL) || defined(__CUDA_ARCH_FEAT_SM100_ALL)
#define TC_ENABLED 1
#else
#define TC_ENABLED 0
#endif

// ---------------- scratch ------------------------------------------------------
__device__ float g_Xr[BATCH*CH*FPAD];
__device__ float g_Xi[BATCH*CH*FPAD];
__device__ float g_Or[BATCH*CH*FPAD];
__device__ float g_Oi[BATCH*CH*FPAD];
__device__ float g_energy[BATCH*NF];
__device__ float g_normv[BATCH*NF];
__device__ float g_med[BATCH];
__device__ float g_thr[1];
__device__ float2 g_tw[4096];
__device__ float g_lsum[BATCH*FT];     /* row sums of e (atomic) */

#define QKN ((size_t)BATCH*FT*CH)     /* [b][f][c] */
#define VN  ((size_t)BATCH*CH*FT)     /* [b][c][g] */
#define PN  ((size_t)BATCH*FT*FT)     /* [b][f][g] */
__device__ __align__(256) __nv_bfloat16 g_qrh[QKN], g_qrl[QKN];
__device__ __align__(256) __nv_bfloat16 g_qih[QKN], g_qil[QKN];
__device__ __align__(256) __nv_bfloat16 g_krh[QKN], g_krl[QKN];
__device__ __align__(256) __nv_bfloat16 g_kih[QKN], g_kil[QKN];
__device__ __align__(256) __nv_bfloat16 g_vrh[VN],  g_vrl[VN];
__device__ __align__(256) __nv_bfloat16 g_vih[VN],  g_vil[VN];
__device__ __align__(256) __nv_bfloat16 g_wkh[CH*CH], g_wkl[CH*CH];
__device__ __align__(256) __nv_bfloat16 g_wvh[CH*CH], g_wvl[CH*CH];
__device__ __align__(256) float g_S[PN];   /* e = exp(|S|*scale) */

// ================= tcgen05 helpers (feature-gated) ============================
__device__ __forceinline__ uint32_t smem_u32(const void* p) {
    uint32_t a;
    asm("{ .reg .u64 t; cvta.to.shared.u64 t, %1; cvt.u32.u64 %0, t; }" : "=r"(a) : "l"(p));
    return a;
}
__device__ __forceinline__ uint32_t elect_one() {
    uint32_t p;
    asm volatile("{ .reg .pred p; elect.sync _|p, 0xFFFFFFFF; selp.b32 %0, 1, 0, p; }" : "=r"(p));
    return p;
}
__device__ __forceinline__ void tc_alloc(uint32_t sa, uint32_t n) {
#if TC_ENABLED
    asm volatile("tcgen05.alloc.cta_group::1.sync.aligned.shared::cta.b32 [%0], %1;" :: "r"(sa), "r"(n) : "memory");
#endif
}
__device__ __forceinline__ void tc_dealloc(uint32_t tm, uint32_t n) {
#if TC_ENABLED
    asm volatile("tcgen05.dealloc.cta_group::1.sync.aligned.b32 %0, %1;" :: "r"(tm), "r"(n));
#endif
}
__device__ __forceinline__ void tc_commit(uint32_t mb) {
#if TC_ENABLED
    asm volatile("tcgen05.commit.cta_group::1.mbarrier::arrive::one.shared::cluster.b64 [%0];" :: "r"(mb) : "memory");
#endif
}
__device__ __forceinline__ void tc_wait_ld() {
#if TC_ENABLED
    asm volatile("tcgen05.wait::ld.sync.aligned;" ::: "memory");
#endif
}
__device__ __forceinline__ void tc_fence_after() {
#if TC_ENABLED
    asm volatile("tcgen05.fence::after_thread_sync;" ::: "memory");
#endif
}
__device__ __forceinline__ void tc_ld_x32(uint32_t* r, uint32_t ta) {
#if TC_ENABLED
    asm volatile("tcgen05.ld.sync.aligned.32x32b.x32.b32 "
        "{%0, %1, %2, %3, %4, %5, %6, %7, %8, %9, %10, %11, %12, %13, %14, %15, "
        " %16, %17, %18, %19, %20, %21, %22, %23, %24, %25, %26, %27, %28, %29, %30, %31}, [%32];"
        : "=r"(r[0]),  "=r"(r[1]),  "=r"(r[2]),  "=r"(r[3]),
          "=r"(r[4]),  "=r"(r[5]),  "=r"(r[6]),  "=r"(r[7]),
          "=r"(r[8]),  "=r"(r[9]),  "=r"(r[10]), "=r"(r[11]),
          "=r"(r[12]), "=r"(r[13]), "=r"(r[14]), "=r"(r[15]),
          "=r"(r[16]), "=r"(r[17]), "=r"(r[18]), "=r"(r[19]),
          "=r"(r[20]), "=r"(r[21]), "=r"(r[22]), "=r"(r[23]),
          "=r"(r[24]), "=r"(r[25]), "=r"(r[26]), "=r"(r[27]),
          "=r"(r[28]), "=r"(r[29]), "=r"(r[30]), "=r"(r[31])
        : "r"(ta));
#else
    for (int i = 0; i < 32; i++) r[i] = 0u;
#endif
}

#define MBAR_INIT(mb, c)  asm volatile("mbarrier.init.shared.b64 [%0], %1;" :: "r"((uint32_t)(mb)), "r"((uint32_t)(c)) : "memory")
#define MBAR_INVAL(mb)    asm volatile("mbarrier.inval.shared.b64 [%0];" :: "r"((uint32_t)(mb)) : "memory")
__device__ __forceinline__ void mbar_wait(uint32_t mb, uint32_t ph) {
#if TC_ENABLED
    asm volatile("{\n\t.reg .pred P1;\n\tWL_%=:\n\t"
        "mbarrier.try_wait.parity.acquire.cta.shared::cta.b64 P1, [%0], %1, 0x989680;\n\t"
        "@P1 bra.uni WD_%=;\n\tbra.uni WL_%=;\n\tWD_%=:\n\t}"
        :: "r"(mb), "r"(ph) : "memory");
#endif
}
#define FENCE_ASYNC()     asm volatile("fence.proxy.async.shared::cta;" ::: "memory")

// cp.async (Ampere+, legal in generic pass)
__device__ __forceinline__ void cp16(uint32_t dst, const void* src) {
    asm volatile("cp.async.cg.shared.global [%0], [%1], 16;" :: "r"(dst), "l"(src));
}
#define CP_COMMIT() asm volatile("cp.async.commit_group;" ::: "memory")
#define CP_WAIT0()  asm volatile("cp.async.wait_group 0;" ::: "memory")

static constexpr uint64_t DESC_BASE_SW128 =
    (uint64_t(2) << 61) | (uint64_t(1) << 46) | (uint64_t(64) << 32) | (uint64_t(1) << 16);
#define MK_DESC(a) (DESC_BASE_SW128 | ((uint64_t)(((uint32_t)(a)) >> 4) & 0x3FFF))
#define QK_IDESC ((1u<<4)|(1u<<7)|(1u<<10)|((128u/8u)<<17)|((128u/16u)<<24))

__device__ __forceinline__ void mma_f16_ss(uint32_t d, uint64_t ad, uint64_t bd, uint32_t idesc, int en) {
#if TC_ENABLED
    asm volatile("{\n\t.reg .pred p;\n\tsetp.ne.u32 p, %4, 0;\n\t"
        "tcgen05.mma.cta_group::1.kind::f16 [%0], %1, %2, %3, {%5, %5, %5, %5}, p;\n\t}"
        :: "r"(d), "l"(ad), "l"(bd), "r"(idesc), "r"((uint32_t)en), "r"(0u) : "memory");
#endif
}

// smem layout (bytes)
#define R_A    0
#define R_B0   65536
#define R_B1   131072
#define R_CTRL 196608
#define MMA_SMEM_BYTES (196608 + 16)
#define STAGE0 0
#define STAGE1 69632

// cp.async load of 4 tiles (hi/lo × khalf), [128 rows][64 bf16], SW128 swizzle
__device__ __forceinline__ void load_tile_pair_ca(uint32_t smb, int region,
        const __nv_bfloat16* __restrict__ hi, const __nv_bfloat16* __restrict__ lo,
        size_t rbase, int rstride) {
    int t = threadIdx.x;
#pragma unroll
    for (int sp = 0; sp < 2; sp++) {
        const __nv_bfloat16* src = sp ? lo : hi;
#pragma unroll
        for (int kh = 0; kh < 2; kh++) {
#pragma unroll
            for (int i = 0; i < 4; i++) {
                int idx = t + i * 256;
                int row = idx >> 3, ch = idx & 7;
                uint32_t off = (uint32_t)(row * 128 + ch * 16);
                off ^= (off >> 3) & 0x70;
                cp16(smb + region + (sp * 2 + kh) * 16384 + off,
                     src + rbase + (size_t)row * rstride + kh * 64 + ch * 8);
            }
        }
    }
}

// 3-chain split MMA: (hi,hi),(hi,lo),(lo,hi), K=128 = 2 khalves × 4 K16 steps
__device__ __forceinline__ void mma_pair(uint32_t d, uint32_t smb, int aoff, int boff, int first) {
    const int asp[3] = {0, 0, 1};
    const int bsp[3] = {0, 1, 0};
#pragma unroll
    for (int s = 0; s < 3; s++) {
#pragma unroll
        for (int kh = 0; kh < 2; kh++) {
            uint64_t ad = MK_DESC(smb + aoff + (asp[s] * 2 + kh) * 16384);
            uint64_t bd = MK_DESC(smb + boff + (bsp[s] * 2 + kh) * 16384);
#pragma unroll
            for (int ks = 0; ks < 4; ks++) {
                int en = !(first && s == 0 && kh == 0 && ks == 0);
                mma_f16_ss(d, ad + ks * 2, bd + ks * 2, QK_IDESC, en);
            }
        }
    }
}

// ---------------- exact k-th order statistic via radix select -----------------
__device__ __forceinline__ float radix_select_smem(const uint32_t* sv, int n, int k,
                                                   uint32_t* hist, int* sh, int nt) {
    int tid = threadIdx.x;
    int n_pad = ((n + nt - 1) / nt) * nt;
    uint32_t prefix = 0;
    int rank = k;
#pragma unroll 1
    for (int shift = 24; shift >= 0; shift -= 8) {
        for (int i = tid; i < 256; i += nt) hist[i] = 0;
        __syncthreads();
        uint32_t pmask = (shift == 24) ? 0u : (0xFFFFFFFFu << (shift + 8));
        for (int i = tid; i < n_pad; i += nt) {
            bool act = false;
            uint32_t bkt = 0x100u;
            if (i < n) {
                uint32_t v = sv[i];
                if ((v & pmask) == prefix) { act = true; bkt = (v >> shift) & 0xFFu; }
            }
            uint32_t grp = __match_any_sync(0xffffffffu, bkt);
            if (act) {
                int leader = __ffs(grp) - 1;
                if ((int)(tid & 31) == leader) atomicAdd(&hist[bkt], __popc(grp));
            }
        }
        __syncthreads();
        if (tid == 0) {
            int acc = 0, bsel = 255;
            for (int bkt = 0; bkt < 256; bkt++) {
                int c = (int)hist[bkt];
                if (acc + c > rank) { bsel = bkt; break; }
                acc += c;
            }
            sh[0] = bsel;
            sh[1] = rank - acc;
        }
        __syncthreads();
        prefix |= ((uint32_t)sh[0]) << shift;
        rank = sh[1];
        __syncthreads();
    }
    return __uint_as_float(prefix);
}

// ---------------- init: twiddles + W split + zero accumulators ----------------
__global__ __launch_bounds__(512) void k_init(const float* __restrict__ WK,
                                              const float* __restrict__ WV) {
    int tid = threadIdx.x;
    for (int idx = tid; idx < 4096; idx += 512) {
        if (idx == 0) { g_tw[0] = make_float2(1.f, 0.f); continue; }
        int s = 31 - __clz(idx);
        int L = 1 << s;
        int k = idx - L;
        float th = 3.14159265358979323846f * (float)k / (float)L;
        g_tw[idx] = make_float2(cosf(th), sinf(th));
    }
    for (int idx = tid; idx < CH * CH; idx += 512) {
        float v = WK[idx];
        __nv_bfloat16 h = __float2bfloat16(v);
        g_wkh[idx] = h;
        g_wkl[idx] = __float2bfloat16(v - __bfloat162float(h));
        v = WV[idx];
        h = __float2bfloat16(v);
        g_wvh[idx] = h;
        g_wvl[idx] = __float2bfloat16(v - __bfloat162float(h));
    }
    for (int idx = tid; idx < BATCH * FT; idx += 512) g_lsum[idx] = 0.f;
    for (int idx = tid; idx < BATCH * NF; idx += 512) g_energy[idx] = 0.f;
}

// ---------------- Stockham radix-2 FFT of 4096 (smem twiddles) ----------------
template <int SIGN>
__device__ __forceinline__ void fft4096(float2* bufA, float2* bufB, const float2* tws) {
    float2* src = bufA;
    float2* dst = bufB;
#pragma unroll 1
    for (int s = 0; s < 12; s++) {
        int L = 1 << s;
        __syncthreads();
        for (int i = threadIdx.x; i < 2048; i += 512) {
            int k = i & (L - 1);
            int j = i >> s;
            float2 u = src[i];
            float2 v = src[i + 2048];
            float2 t = tws[L + k];
            float cw = t.x, sw = (float)SIGN * t.y;
            float2 wv = make_float2(cw * v.x - sw * v.y, cw * v.y + sw * v.x);
            int o = (j << (s + 1)) + k;
            dst[o]     = make_float2(u.x + wv.x, u.y + wv.y);
            dst[o + L] = make_float2(u.x - wv.x, u.y - wv.y);
        }
        float2* t2 = src; src = dst; dst = t2;
    }
    __syncthreads();
}

#define FFT_SMEM (3 * 4096 * sizeof(float2))

__global__ __launch_bounds__(512) void k_fft_fwd(const float* __restrict__ x_in) {
    extern __shared__ float2 sm2[];
    float2* A = sm2;
    float2* Bb = sm2 + 4096;
    float2* tws = sm2 + 8192;
    for (int i = threadIdx.x; i < 4096; i += 512) tws[i] = g_tw[i];
    int bc = blockIdx.x;
    const float* xrow = x_in + (size_t)bc * NT;
    for (int k = threadIdx.x; k < 4096; k += 512) A[k] = make_float2(xrow[k], 0.f);
    fft4096<-1>(A, Bb, tws);
    const float s = 1.0f / SQRTN;
    size_t base = (size_t)bc * FPAD;
    for (int f = threadIdx.x; f < NF; f += 512) {
        g_Xr[base + f] = A[f].x * s;
        g_Xi[base + f] = A[f].y * s;
    }
}

// ------- fp32 X [c][f] -> bf16 hi/lo [f][c] (transpose + split) + energy ------
__global__ __launch_bounds__(256) void k_conv_qk() {
    __shared__ float ts[64][65];
    int ftile = blockIdx.x;            // 0..33
    int b = blockIdx.y >> 1;
    int ch0 = (blockIdx.y & 1) * 64;
    int w = blockIdx.z;                // 0: Xr, 1: Xi
    const float* src = w ? g_Xi : g_Xr;
    __nv_bfloat16* dh = w ? g_qih : g_qrh;
    __nv_bfloat16* dl = w ? g_qil : g_qrl;
    int f0 = ftile * 64;
    size_t sbase = (size_t)b * CH * FPAD;
    int tid = threadIdx.x;
    for (int idx = tid; idx < 4096; idx += 256) {
        int c = idx >> 6, f = idx & 63;
        int gf = f0 + f;
        float v = (gf < NF) ? src[sbase + (size_t)(ch0 + c) * FPAD + gf] : 0.f;
        ts[f][c] = v;
    }
    __syncthreads();
    // energy partial: sum over this 64-channel half of v^2, atomic to g_energy
    {
        int fl = tid >> 2, q = tid & 3;
        float s = 0.f;
#pragma unroll
        for (int j = 0; j < 16; j++) {
            float v = ts[fl][q * 16 + j];
            s = fmaf(v, v, s);
        }
        s += __shfl_down_sync(0xffffffffu, s, 2, 4);
        s += __shfl_down_sync(0xffffffffu, s, 1, 4);
        int gf = f0 + fl;
        if (q == 0 && gf < NF) atomicAdd(&g_energy[b * NF + gf], s);
    }
    for (int idx = tid; idx < 4096; idx += 256) {
        int f = idx >> 6, c = idx & 63;
        float v = ts[f][c];
        __nv_bfloat16 h = __float2bfloat16(v);
        size_t o = ((size_t)b * FT + f0 + f) * CH + ch0 + c;
        dh[o] = h;
        dl[o] = __float2bfloat16(v - __bfloat162float(h));
    }
}

// ---------------- K/V = W x X via tcgen05, bf16 hi/lo outputs -----------------
__global__ __launch_bounds__(256, 1) __cluster_dims__(1, 1, 1)
void k_kv_mma(const float* __restrict__ bK, const float* __restrict__ bV) {
    extern __shared__ char sm[];
    uint32_t smb = smem_u32(sm);
    int tid = threadIdx.x, wid = tid >> 5, lane = tid & 31;
    int f0 = blockIdx.x * 128, b = blockIdx.y, kv = blockIdx.z;

    if (wid == 0) tc_alloc(smb + R_CTRL, 256);
    if (tid == 0) MBAR_INIT(smb + R_CTRL + 8, 1);
    __syncthreads();
    uint32_t tm;
    asm volatile("ld.shared.b32 %0, [%1];" : "=r"(tm) : "r"(smb + R_CTRL));
    uint32_t mbar = smb + R_CTRL + 8;

    const __nv_bfloat16* wh = kv ? g_wvh : g_wkh;
    const __nv_bfloat16* wl = kv ? g_wvl : g_wkl;
    load_tile_pair_ca(smb, R_A, wh, wl, 0, CH);
    size_t xb = ((size_t)b * FT + f0) * CH;
    load_tile_pair_ca(smb, R_B0, g_qrh, g_qrl, xb, CH);
    load_tile_pair_ca(smb, R_B1, g_qih, g_qil, xb, CH);
    CP_COMMIT(); CP_WAIT0();
    FENCE_ASYNC();
    __syncthreads();

    if (wid == 0 && elect_one()) {
        mma_pair(tm, smb, R_A, R_B0, 1);        // D0 = W x Xr
        mma_pair(tm + 128, smb, R_A, R_B1, 1);  // D1 = W x Xi
        tc_commit(mbar);
    }
    mbar_wait(mbar, 0);
    tc_fence_after();

    // stage D0 (warps 0-3) / D1 (warps 4-7) fp32 [m][f], stride 133
    {
        int half = wid >> 2, w4 = wid & 3;
        float* stage = (float*)(sm + (half ? STAGE1 : STAGE0));
        uint32_t dbase = tm + half * 128;
        int row = w4 * 32 + lane;
#pragma unroll
        for (int part = 0; part < 4; part++) {
            uint32_t r[32];
            tc_ld_x32(r, dbase + part * 32);
            tc_wait_ld();
#pragma unroll
            for (int c = 0; c < 32; c++) stage[row * 133 + part * 32 + c] = __uint_as_float(r[c]);
        }
    }
    __syncthreads();
    const float* s0 = (const float*)(sm + STAGE0);
    const float* s1 = (const float*)(sm + STAGE1);
    if (kv == 0) {
        // K: transposed write [f][c]
        for (int idx = tid; idx < 128 * 128; idx += 256) {
            int f = idx >> 7, c = idx & 127;
            float vr = s0[c * 133 + f];
            float vi = s1[c * 133 + f];
            if (f0 == 0 && f == 0) vr += SQRTN * __ldg(&bK[c]);
            size_t o = ((size_t)b * FT + f0 + f) * CH + c;
            __nv_bfloat16 h = __float2bfloat16(vr);
            g_krh[o] = h;
            g_krl[o] = __float2bfloat16(vr - __bfloat162float(h));
            h = __float2bfloat16(vi);
            g_kih[o] = h;
            g_kil[o] = __float2bfloat16(vi - __bfloat162float(h));
        }
    } else {
        // V: direct write [c][g]
        for (int idx = tid; idx < 128 * 128; idx += 256) {
            int c = idx >> 7, f = idx & 127;
            float vr = s0[c * 133 + f];
            float vi = s1[c * 133 + f];
            if (f0 == 0 && f == 0) vr += SQRTN * __ldg(&bV[c]);
            size_t o = ((size_t)b * CH + c) * FT + f0 + f;
            __nv_bfloat16 h = __float2bfloat16(vr);
            g_vrh[o] = h;
            g_vrl[o] = __float2bfloat16(vr - __bfloat162float(h));
            h = __float2bfloat16(vi);
            g_vih[o] = h;
            g_vil[o] = __float2bfloat16(vi - __bfloat162float(h));
        }
    }
    __syncthreads();
    if (tid == 0) MBAR_INVAL(mbar);
    __syncthreads();
    if (wid == 0) tc_dealloc(tm, 256);
}

// ------- QK^T via tcgen05 (4 accums), e = exp(|S|*scale), fused row sums ------
__global__ __launch_bounds__(256, 1) __cluster_dims__(1, 1, 1) void k_qk_mma() {
    extern __shared__ char sm[];
    uint32_t smb = smem_u32(sm);
    int tid = threadIdx.x, wid = tid >> 5, lane = tid & 31;
    int g0 = blockIdx.x * 128, f0 = blockIdx.y * 128, b = blockIdx.z;

    if (wid == 0) tc_alloc(smb + R_CTRL, 512);
    if (tid == 0) MBAR_INIT(smb + R_CTRL + 8, 1);
    __syncthreads();
    uint32_t tm;
    asm volatile("ld.shared.b32 %0, [%1];" : "=r"(tm) : "r"(smb + R_CTRL));
    uint32_t mbar = smb + R_CTRL + 8;

    size_t kb = ((size_t)b * FT + g0) * CH;
    size_t qb = ((size_t)b * FT + f0) * CH;
    load_tile_pair_ca(smb, R_B0, g_krh, g_krl, kb, CH);
    load_tile_pair_ca(smb, R_B1, g_kih, g_kil, kb, CH);
    load_tile_pair_ca(smb, R_A, g_qrh, g_qrl, qb, CH);
    CP_COMMIT(); CP_WAIT0();
    FENCE_ASYNC();
    __syncthreads();

    uint32_t phase = 0;
    if (wid == 0 && elect_one()) {
        mma_pair(tm, smb, R_A, R_B0, 1);        // D0 = Qr*Kr
        mma_pair(tm + 128, smb, R_A, R_B1, 1);  // D1 = Qr*Ki
        tc_commit(mbar);
    }
    mbar_wait(mbar, phase); phase ^= 1;

    load_tile_pair_ca(smb, R_A, g_qih, g_qil, qb, CH);
    CP_COMMIT(); CP_WAIT0();
    FENCE_ASYNC();
    __syncthreads();
    if (wid == 0 && elect_one()) {
        mma_pair(tm + 256, smb, R_A, R_B1, 1);  // D2 = Qi*Ki
        mma_pair(tm + 384, smb, R_A, R_B0, 1);  // D3 = Qi*Kr
        tc_commit(mbar);
    }
    mbar_wait(mbar, phase); phase ^= 1;
    tc_fence_after();

    // warps 0-3: sr = D0 - D2 -> STAGE0; warps 4-7: si = D1 + D3 -> STAGE1
    {
        int half = wid >> 2, w4 = wid & 3;
        float* stage = (float*)(sm + (half ? STAGE1 : STAGE0));
        uint32_t dA = tm + (half ? 128 : 0);
        uint32_t dB = tm + (half ? 384 : 256);
        int row = w4 * 32 + lane;
#pragma unroll
        for (int part = 0; part < 4; part++) {
            uint32_t ra[32], rb[32];
            tc_ld_x32(ra, dA + part * 32);
            tc_ld_x32(rb, dB + part * 32);
            tc_wait_ld();
#pragma unroll
            for (int c = 0; c < 32; c++) {
                float fa = __uint_as_float(ra[c]);
                float fb = __uint_as_float(rb[c]);
                stage[row * 132 + part * 32 + c] = half ? (fa + fb) : (fa - fb);
            }
        }
    }
    __syncthreads();
    {
        const float* str = (const float*)(sm + STAGE0);
        const float* sti = (const float*)(sm + STAGE1);
        size_t sbase = ((size_t)b * FT + f0) * FT + g0;
        for (int idx = tid; idx < 128 * 128; idx += 256) {
            int row = idx >> 7, col = idx & 127;
            float sr = str[row * 132 + col], si = sti[row * 132 + col];
            float u = fmaxf(fmaf(sr, sr, si * si), 1e-30f);
            float y = __int_as_float(0x5f3759df - (__float_as_int(u) >> 1));
            float hu = 0.5f * u;
            y = y * (1.5f - hu * y * y);
            y = y * (1.5f - hu * y * y);
            float m = u * y;
            float e = (g0 + col < NF) ? __expf(m * ATT_SCALE) : 0.f;
            g_S[sbase + (size_t)row * FT + col] = e;
            // fused row-sum (all lanes in warp share `row`)
            float s = e;
#pragma unroll
            for (int mm = 16; mm; mm >>= 1) s += __shfl_xor_sync(0xffffffffu, s, mm);
            if (lane == 0) atomicAdd(&g_lsum[(size_t)b * FT + f0 + row], s);
        }
    }
    __syncthreads();
    if (tid == 0) MBAR_INVAL(mbar);
    __syncthreads();
    if (wid == 0) tc_dealloc(tm, 512);
}

// ---------------- O = P @ V via tcgen05; P built on-the-fly -------------------
__global__ __launch_bounds__(256, 1) __cluster_dims__(1, 1, 1) void k_av_mma() {
    extern __shared__ char sm[];
    __shared__ float invl_s[128];
    uint32_t smb = smem_u32(sm);
    int tid = threadIdx.x, wid = tid >> 5, lane = tid & 31;
    int f0 = blockIdx.x * 128, b = blockIdx.y;
    if (wid == 0) tc_alloc(smb + R_CTRL, 256);
    if (tid == 0) MBAR_INIT(smb + R_CTRL + 8, 1);
    if (tid < 128) {
        float ls = g_lsum[(size_t)b * FT + f0 + tid];
        invl_s[tid] = (ls > 0.f) ? 1.0f / ls : 0.f;
    }
    __syncthreads();
    uint32_t tm;
    asm volatile("ld.shared.b32 %0, [%1];" : "=r"(tm) : "r"(smb + R_CTRL));
    uint32_t mbar = smb + R_CTRL + 8;
    uint32_t phase = 0;
    for (int kt = 0; kt < 17; kt++) {
        int g0 = kt * 128;
        // async V loads first (overlap with P build below)
        size_t vb = ((size_t)b * CH) * FT + g0;
        load_tile_pair_ca(smb, R_B0, g_vrh, g_vrl, vb, FT);
        load_tile_pair_ca(smb, R_B1, g_vih, g_vil, vb, FT);
        CP_COMMIT();
        // build A = P tile (bf16 hi/lo, swizzled) from e * invl
#pragma unroll
        for (int i = 0; i < 8; i++) {
            int chunk = tid + i * 256;
            int row = chunk >> 4, c8 = (chunk & 15) * 8;
            const float* srow = g_S + ((size_t)b * FT + f0 + row) * FT + g0 + c8;
            float4 ea = *(const float4*)srow;
            float4 eb = *(const float4*)(srow + 4);
            float iv = invl_s[row];
            float pv[8] = {ea.x * iv, ea.y * iv, ea.z * iv, ea.w * iv,
                           eb.x * iv, eb.y * iv, eb.z * iv, eb.w * iv};
            uint32_t hiw[4], low[4];
#pragma unroll
            for (int j = 0; j < 4; j++) {
                __nv_bfloat162 h2 = __floats2bfloat162_rn(pv[2 * j], pv[2 * j + 1]);
                hiw[j] = *(uint32_t*)&h2;
                float l0 = pv[2 * j]     - __bfloat162float(__low2bfloat16(h2));
                float l1 = pv[2 * j + 1] - __bfloat162float(__high2bfloat16(h2));
                __nv_bfloat162 l2 = __floats2bfloat162_rn(l0, l1);
                low[j] = *(uint32_t*)&l2;
            }
            int kh = c8 >> 6;
            uint32_t off = (uint32_t)(row * 128 + (c8 & 63) * 2);
            off ^= (off >> 3) & 0x70;
            *(uint4*)(sm + R_A + kh * 16384 + off)       = make_uint4(hiw[0], hiw[1], hiw[2], hiw[3]);
            *(uint4*)(sm + R_A + (2 + kh) * 16384 + off) = make_uint4(low[0], low[1], low[2], low[3]);
        }
        CP_WAIT0();
        FENCE_ASYNC();
        __syncthreads();
        if (wid == 0 && elect_one()) {
            mma_pair(tm, smb, R_A, R_B0, kt == 0);        // Or += P*Vr
            mma_pair(tm + 128, smb, R_A, R_B1, kt == 0);  // Oi += P*Vi
            tc_commit(mbar);
        }
        mbar_wait(mbar, phase); phase ^= 1;
    }
    tc_fence_after();
    {
        int half = wid >> 2, w4 = wid & 3;
        float* stage = (float*)(sm + (half ? STAGE1 : STAGE0));
        uint32_t dbase = tm + half * 128;
        int row = w4 * 32 + lane;
#pragma unroll
        for (int part = 0; part < 4; part++) {
            uint32_t r[32];
            tc_ld_x32(r, dbase + part * 32);
            tc_wait_ld();
#pragma unroll
            for (int c = 0; c < 32; c++) stage[row * 132 + part * 32 + c] = __uint_as_float(r[c]);
        }
    }
    __syncthreads();
    {
        const float* str = (const float*)(sm + STAGE0);
        const float* sti = (const float*)(sm + STAGE1);
        for (int idx = tid; idx < 128 * 128; idx += 256) {
            int c = idx >> 7, fl = idx & 127;
            int gf = f0 + fl;
            if (gf < NF) {
                size_t o = ((size_t)b * CH + c) * FPAD + gf;
                g_Or[o] = str[fl * 132 + c];
                g_Oi[o] = sti[fl * 132 + c];
            }
        }
    }
    __syncthreads();
    if (tid == 0) MBAR_INVAL(mbar);
    __syncthreads();
    if (wid == 0) tc_dealloc(tm, 256);
}

// ---------------- median (exact radix select per batch) -----------------------
__global__ __launch_bounds__(256) void k_median() {
    __shared__ uint32_t sv[NF];
    __shared__ uint32_t hist[256];
    __shared__ int sh[2];
    int b = blockIdx.x;
    for (int i = threadIdx.x; i < NF; i += 256) sv[i] = __float_as_uint(g_energy[b * NF + i]);
    __syncthreads();
    float m = radix_select_smem(sv, NF, NF / 2, hist, sh, 256);
    if (threadIdx.x == 0) g_med[b] = m;
}

// ------- global quantile (fused normalize; exact radix select) ----------------
#define QSEL_N (BATCH * NF)
#define QSEL_SMEM ((QSEL_N + 256 + 2) * 4)
__global__ __launch_bounds__(512) void k_quantile(const float* __restrict__ qparam) {
    extern __shared__ uint32_t qsm[];
    uint32_t* sv = qsm;
    uint32_t* hist = qsm + QSEL_N;
    int* sh = (int*)(hist + 256);
    for (int i = threadIdx.x; i < QSEL_N; i += 512) {
        int b = i / NF;
        float v = g_energy[i] / (g_med[b] + 1e-6f);
        g_normv[i] = v;
        sv[i] = __float_as_uint(v);
    }
    __syncthreads();
    float q = qparam[0];
    float pos = q * (float)(QSEL_N - 1);
    int lo = (int)floorf(pos);
    if (lo < 0) lo = 0;
    if (lo > QSEL_N - 2) lo = QSEL_N - 2;
    float frac = pos - (float)lo;
    float a = radix_select_smem(sv, QSEL_N, lo, hist, sh, 512);
    __syncthreads();
    float bb = radix_select_smem(sv, QSEL_N, lo + 1, hist, sh, 512);
    if (threadIdx.x == 0) g_thr[0] = a + (bb - a) * frac;
}

// ---------------- inverse rfft (fused hi-freq mask) -> output (B,C,N) ---------
__global__ __launch_bounds__(512) void k_ifft(float* __restrict__ out,
                                              const float* __restrict__ w_high) {
    extern __shared__ float2 sm2[];
    float2* A = sm2;
    float2* Bb = sm2 + 4096;
    float2* tws = sm2 + 8192;
    for (int i = threadIdx.x; i < 4096; i += 512) tws[i] = g_tw[i];
    int bc = blockIdx.x;
    int b = bc >> 7, c = bc & 127;
    float whr = w_high[c * 2], whi = w_high[c * 2 + 1];
    float thr = g_thr[0];
    size_t base = (size_t)bc * FPAD;
    for (int k = threadIdx.x; k < 4096; k += 512) {
        int kk = (k <= 2048) ? k : (4096 - k);
        float sgn = (k <= 2048) ? 1.f : -1.f;
        float oR = g_Or[base + kk];
        float oI = g_Oi[base + kk];
        if (g_normv[b * NF + kk] > thr) {
            float xr = g_Xr[base + kk], xi = g_Xi[base + kk];
            oR += xr * whr - xi * whi;
            oI += xr * whi + xi * whr;
        }
        A[k] = make_float2(oR, sgn * oI);
    }
    fft4096<1>(A, Bb, tws);
    const float s = 1.0f / SQRTN;
    float* orow = out + (size_t)bc * NT;
    for (int n = threadIdx.x; n < 4096; n += 512) orow[n] = A[n].x * s;
}

// ---------------- launch -------------------------------------------------------
extern "C" void kernel_launch(void* const* d_in, const int* in_sizes, int n_in,
                              void* d_out, int out_size) {
    const float* x_in   = (const float*)d_in[0];
    const float* W_K    = (const float*)d_in[1];
    const float* b_K    = (const float*)d_in[2];
    const float* W_V    = (const float*)d_in[3];
    const float* b_V    = (const float*)d_in[4];
    const float* w_high = (const float*)d_in[5];
    const float* qparam = (const float*)d_in[6];
    float* out = (float*)d_out;

    cudaFuncSetAttribute(k_fft_fwd,  cudaFuncAttributeMaxDynamicSharedMemorySize, FFT_SMEM);
    cudaFuncSetAttribute(k_ifft,     cudaFuncAttributeMaxDynamicSharedMemorySize, FFT_SMEM);
    cudaFuncSetAttribute(k_kv_mma,   cudaFuncAttributeMaxDynamicSharedMemorySize, MMA_SMEM_BYTES);
    cudaFuncSetAttribute(k_qk_mma,   cudaFuncAttributeMaxDynamicSharedMemorySize, MMA_SMEM_BYTES);
    cudaFuncSetAttribute(k_av_mma,   cudaFuncAttributeMaxDynamicSharedMemorySize, MMA_SMEM_BYTES);
    cudaFuncSetAttribute(k_quantile, cudaFuncAttributeMaxDynamicSharedMemorySize, QSEL_SMEM);

    k_init<<<1, 512>>>(W_K, W_V);
    k_fft_fwd<<<BATCH * CH, 512, FFT_SMEM>>>(x_in);
    k_conv_qk<<<dim3(34, 16, 2), 256>>>();
    k_kv_mma<<<dim3(17, 8, 2), 256, MMA_SMEM_BYTES>>>(b_K, b_V);
    k_qk_mma<<<dim3(17, 17, 8), 256, MMA_SMEM_BYTES>>>();
    k_av_mma<<<dim3(17, 8), 256, MMA_SMEM_BYTES>>>();
    k_median<<<BATCH, 256>>>();
    k_quantile<<<1, 512, QSEL_SMEM>>>(qparam);
    k_ifft<<<BATCH * CH, 512, FFT_SMEM>>>(out, w_high);
}